// round 1
// baseline (speedup 1.0000x reference)
#include <cuda_runtime.h>
#include <math.h>

#define H     1024
#define INTER 4096
#define NE    8
#define TT    8192   // 4 * 2048 tokens
#define LNEPS 1e-5f

// ---------------- scratch (static device globals; no runtime allocation) ----
__device__ float g_tn[(size_t)TT * H];                 // 32 MB: LN1 out, then LN2 out
__device__ float g_act[(size_t)TT * 2 * INTER];        // 256 MB: silu(g)*u rows, indexed by pair p = t*2+k
__device__ int   g_cnt[NE];
__device__ int   g_list[NE * TT];                      // pair code p = token*2 + slot
__device__ float g_w[NE * TT];                         // combine weight per pair

// ---------------------------------------------------------------------------
__global__ void zero_cnt_kernel() {
    if (threadIdx.x < NE) g_cnt[threadIdx.x] = 0;
}

// LayerNorm: one block per row, 256 threads, H=1024 -> one float4/thread.
// Writes result into g_tn.
__global__ void __launch_bounds__(256) ln_kernel(const float* __restrict__ src,
                                                 const float* __restrict__ gamma,
                                                 const float* __restrict__ beta) {
    int row = blockIdx.x;
    int tid = threadIdx.x;
    const float4 xv = ((const float4*)(src + (size_t)row * H))[tid];
    float s = xv.x + xv.y + xv.z + xv.w;
    float q = xv.x * xv.x + xv.y * xv.y + xv.z * xv.z + xv.w * xv.w;
#pragma unroll
    for (int o = 16; o; o >>= 1) {
        s += __shfl_xor_sync(0xffffffffu, s, o);
        q += __shfl_xor_sync(0xffffffffu, q, o);
    }
    __shared__ float ss[8], sq[8];
    __shared__ float sm, sr;
    int w = tid >> 5;
    if ((tid & 31) == 0) { ss[w] = s; sq[w] = q; }
    __syncthreads();
    if (tid == 0) {
        float S = 0.f, Q = 0.f;
#pragma unroll
        for (int i = 0; i < 8; ++i) { S += ss[i]; Q += sq[i]; }
        float m = S * (1.0f / H);
        float v = Q * (1.0f / H) - m * m;
        sm = m;
        sr = rsqrtf(v + LNEPS);
    }
    __syncthreads();
    float m = sm, r = sr;
    const float4 gv = ((const float4*)gamma)[tid];
    const float4 bv = ((const float4*)beta)[tid];
    float4 o;
    o.x = (xv.x - m) * r * gv.x + bv.x;
    o.y = (xv.y - m) * r * gv.y + bv.y;
    o.z = (xv.z - m) * r * gv.z + bv.z;
    o.w = (xv.w - m) * r * gv.w + bv.w;
    ((float4*)(g_tn + (size_t)row * H))[tid] = o;
}

// attn GEMM: C[m,n] = x[m,n] + sum_h tn[m,h] * W[n,h]   (NT layout, K=H=1024)
// Tile 128x128x16, 256 threads, 8x8 microtile.
__global__ void __launch_bounds__(256) attn_gemm_kernel(const float* __restrict__ W,
                                                        const float* __restrict__ X,
                                                        float* __restrict__ C) {
    __shared__ float As[16][132];
    __shared__ float Bs[16][132];
    int bm = blockIdx.x, bn = blockIdx.y;
    int tid = threadIdx.x;
    int tx = tid & 15, ty = tid >> 4;
    float acc[8][8] = {};
    const float* Ab = g_tn + (size_t)(bm * 128) * H;
    const float* Bb = W + (size_t)(bn * 128) * H;
    for (int k0 = 0; k0 < H; k0 += 16) {
#pragma unroll
        for (int s = 0; s < 2; ++s) {
            int q = tid + s * 256;       // 0..511
            int r = q >> 2, c = q & 3;   // r: 0..127 rows, c: 0..3 float4 within 16 k
            float4 av = *(const float4*)(Ab + (size_t)r * H + k0 + c * 4);
            As[c * 4 + 0][r] = av.x; As[c * 4 + 1][r] = av.y;
            As[c * 4 + 2][r] = av.z; As[c * 4 + 3][r] = av.w;
            float4 bv = *(const float4*)(Bb + (size_t)r * H + k0 + c * 4);
            Bs[c * 4 + 0][r] = bv.x; Bs[c * 4 + 1][r] = bv.y;
            Bs[c * 4 + 2][r] = bv.z; Bs[c * 4 + 3][r] = bv.w;
        }
        __syncthreads();
#pragma unroll
        for (int kk = 0; kk < 16; ++kk) {
            float a[8], b[8];
            *(float4*)&a[0] = *(const float4*)&As[kk][ty * 8];
            *(float4*)&a[4] = *(const float4*)&As[kk][ty * 8 + 4];
            *(float4*)&b[0] = *(const float4*)&Bs[kk][tx * 8];
            *(float4*)&b[4] = *(const float4*)&Bs[kk][tx * 8 + 4];
#pragma unroll
            for (int i = 0; i < 8; ++i)
#pragma unroll
                for (int j = 0; j < 8; ++j) acc[i][j] += a[i] * b[j];
        }
        __syncthreads();
    }
#pragma unroll
    for (int i = 0; i < 8; ++i) {
        int m = bm * 128 + ty * 8 + i;
#pragma unroll
        for (int j = 0; j < 8; j += 4) {
            int n = bn * 128 + tx * 8 + j;
            float4 xv = *(const float4*)(X + (size_t)m * H + n);
            float4 o;
            o.x = xv.x + acc[i][j + 0];
            o.y = xv.y + acc[i][j + 1];
            o.z = xv.z + acc[i][j + 2];
            o.w = xv.w + acc[i][j + 3];
            *(float4*)(C + (size_t)m * H + n) = o;
        }
    }
}

// Gate + top-2 + softmax + scatter into per-expert lists. One warp per token.
__global__ void __launch_bounds__(256) gate_topk_kernel(const float* __restrict__ gw) {
    int t = (blockIdx.x * blockDim.x + threadIdx.x) >> 5;
    int lane = threadIdx.x & 31;
    if (t >= TT) return;
    const float* trow = g_tn + (size_t)t * H;
    float lg[NE];
#pragma unroll
    for (int e = 0; e < NE; ++e) {
        float s = 0.f;
        for (int j = lane; j < H; j += 32) s += trow[j] * gw[e * H + j];
#pragma unroll
        for (int o = 16; o; o >>= 1) s += __shfl_xor_sync(0xffffffffu, s, o);
        lg[e] = s;
    }
    if (lane == 0) {
        float v0 = -INFINITY; int i0 = 0;
#pragma unroll
        for (int e = 0; e < NE; ++e) if (lg[e] > v0) { v0 = lg[e]; i0 = e; }
        float v1 = -INFINITY; int i1 = 0;
#pragma unroll
        for (int e = 0; e < NE; ++e) if (e != i0 && lg[e] > v1) { v1 = lg[e]; i1 = e; }
        float ex = expf(v1 - v0);
        float w0 = 1.0f / (1.0f + ex);
        float w1 = ex / (1.0f + ex);
        int p0 = atomicAdd(&g_cnt[i0], 1);
        g_list[i0 * TT + p0] = t * 2 + 0;
        g_w[i0 * TT + p0] = w0;
        int p1 = atomicAdd(&g_cnt[i1], 1);
        g_list[i1 * TT + p1] = t * 2 + 1;
        g_w[i1 * TT + p1] = w1;
    }
}

// MLP-1: for expert e, gathered rows of tn, compute gate & up (NT, K=H),
// act = silu(g)*u -> g_act[pair, :]. Tile 128(M) x 64(N of INTER) x 16(K).
__global__ void __launch_bounds__(256) mlp1_kernel(const float* __restrict__ gate_proj,
                                                   const float* __restrict__ up_proj) {
    int e = blockIdx.z;
    int cnt = g_cnt[e];
    int bm = blockIdx.x;
    if (bm * 128 >= cnt) return;
    __shared__ float As[16][132];
    __shared__ float Gs[16][68];
    __shared__ float Us[16][68];
    __shared__ int sp[128];
    int tid = threadIdx.x;
    if (tid < 128) {
        int r = bm * 128 + tid;
        sp[tid] = (r < cnt) ? g_list[e * TT + r] : -1;
    }
    __syncthreads();
    int tx = tid & 15, ty = tid >> 4;
    // per-thread fixed gather rows for A loads (rows r and r+64)
    int ra = tid >> 2, ca = tid & 3;
    int pa0 = sp[ra];       int t0 = (pa0 < 0) ? 0 : (pa0 >> 1);
    int pa1 = sp[ra + 64];  int t1 = (pa1 < 0) ? 0 : (pa1 >> 1);
    const float* arow0 = g_tn + (size_t)t0 * H + ca * 4;
    const float* arow1 = g_tn + (size_t)t1 * H + ca * 4;
    const float* Gb = gate_proj + (size_t)e * INTER * H + (size_t)(blockIdx.y * 64) * H;
    const float* Ub = up_proj   + (size_t)e * INTER * H + (size_t)(blockIdx.y * 64) * H;
    float accg[8][4] = {}, accu[8][4] = {};
    for (int k0 = 0; k0 < H; k0 += 16) {
        float4 av0 = *(const float4*)(arow0 + k0);
        As[ca * 4 + 0][ra] = av0.x; As[ca * 4 + 1][ra] = av0.y;
        As[ca * 4 + 2][ra] = av0.z; As[ca * 4 + 3][ra] = av0.w;
        float4 av1 = *(const float4*)(arow1 + k0);
        As[ca * 4 + 0][ra + 64] = av1.x; As[ca * 4 + 1][ra + 64] = av1.y;
        As[ca * 4 + 2][ra + 64] = av1.z; As[ca * 4 + 3][ra + 64] = av1.w;
        {
            int r = tid >> 2, c = tid & 3;   // r: 0..63
            float4 gv = *(const float4*)(Gb + (size_t)r * H + k0 + c * 4);
            Gs[c * 4 + 0][r] = gv.x; Gs[c * 4 + 1][r] = gv.y;
            Gs[c * 4 + 2][r] = gv.z; Gs[c * 4 + 3][r] = gv.w;
            float4 uv = *(const float4*)(Ub + (size_t)r * H + k0 + c * 4);
            Us[c * 4 + 0][r] = uv.x; Us[c * 4 + 1][r] = uv.y;
            Us[c * 4 + 2][r] = uv.z; Us[c * 4 + 3][r] = uv.w;
        }
        __syncthreads();
#pragma unroll
        for (int kk = 0; kk < 16; ++kk) {
            float a[8], bg[4], bu[4];
            *(float4*)&a[0] = *(const float4*)&As[kk][ty * 8];
            *(float4*)&a[4] = *(const float4*)&As[kk][ty * 8 + 4];
            *(float4*)&bg[0] = *(const float4*)&Gs[kk][tx * 4];
            *(float4*)&bu[0] = *(const float4*)&Us[kk][tx * 4];
#pragma unroll
            for (int i = 0; i < 8; ++i)
#pragma unroll
                for (int j = 0; j < 4; ++j) {
                    accg[i][j] += a[i] * bg[j];
                    accu[i][j] += a[i] * bu[j];
                }
        }
        __syncthreads();
    }
#pragma unroll
    for (int i = 0; i < 8; ++i) {
        int r = ty * 8 + i;
        int p = sp[r];
        if (p < 0) continue;
        float* dst = g_act + (size_t)p * INTER + blockIdx.y * 64 + tx * 4;
        float4 o;
        float g0 = accg[i][0], g1 = accg[i][1], g2 = accg[i][2], g3 = accg[i][3];
        o.x = (g0 / (1.0f + expf(-g0))) * accu[i][0];
        o.y = (g1 / (1.0f + expf(-g1))) * accu[i][1];
        o.z = (g2 / (1.0f + expf(-g2))) * accu[i][2];
        o.w = (g3 / (1.0f + expf(-g3))) * accu[i][3];
        *(float4*)dst = o;
    }
}

// MLP-2: for expert e, C[m,h] = sum_i act[pair_m, i] * down[e][h, i]; scale by
// combine weight and atomicAdd into output (which already holds h).
// Tile 128x128x16, K = INTER = 4096.
__global__ void __launch_bounds__(256) mlp2_kernel(const float* __restrict__ down_proj,
                                                   float* __restrict__ C) {
    int e = blockIdx.z;
    int cnt = g_cnt[e];
    int bm = blockIdx.x;
    if (bm * 128 >= cnt) return;
    __shared__ float As[16][132];
    __shared__ float Bs[16][132];
    __shared__ int sp[128];
    __shared__ float sw[128];
    int tid = threadIdx.x;
    if (tid < 128) {
        int r = bm * 128 + tid;
        int valid = (r < cnt);
        sp[tid] = valid ? g_list[e * TT + r] : -1;
        sw[tid] = valid ? g_w[e * TT + r] : 0.f;
    }
    __syncthreads();
    int tx = tid & 15, ty = tid >> 4;
    int ra = tid >> 2, ca = tid & 3;
    int pa0 = sp[ra];       int q0 = (pa0 < 0) ? 0 : pa0;
    int pa1 = sp[ra + 64];  int q1 = (pa1 < 0) ? 0 : pa1;
    const float* arow0 = g_act + (size_t)q0 * INTER + ca * 4;
    const float* arow1 = g_act + (size_t)q1 * INTER + ca * 4;
    const float* Bb = down_proj + (size_t)e * H * INTER + (size_t)(blockIdx.y * 128) * INTER;
    float acc[8][8] = {};
    for (int k0 = 0; k0 < INTER; k0 += 16) {
        float4 av0 = *(const float4*)(arow0 + k0);
        As[ca * 4 + 0][ra] = av0.x; As[ca * 4 + 1][ra] = av0.y;
        As[ca * 4 + 2][ra] = av0.z; As[ca * 4 + 3][ra] = av0.w;
        float4 av1 = *(const float4*)(arow1 + k0);
        As[ca * 4 + 0][ra + 64] = av1.x; As[ca * 4 + 1][ra + 64] = av1.y;
        As[ca * 4 + 2][ra + 64] = av1.z; As[ca * 4 + 3][ra + 64] = av1.w;
#pragma unroll
        for (int s = 0; s < 2; ++s) {
            int q = tid + s * 256;
            int r = q >> 2, c = q & 3;
            float4 bv = *(const float4*)(Bb + (size_t)r * INTER + k0 + c * 4);
            Bs[c * 4 + 0][r] = bv.x; Bs[c * 4 + 1][r] = bv.y;
            Bs[c * 4 + 2][r] = bv.z; Bs[c * 4 + 3][r] = bv.w;
        }
        __syncthreads();
#pragma unroll
        for (int kk = 0; kk < 16; ++kk) {
            float a[8], b[8];
            *(float4*)&a[0] = *(const float4*)&As[kk][ty * 8];
            *(float4*)&a[4] = *(const float4*)&As[kk][ty * 8 + 4];
            *(float4*)&b[0] = *(const float4*)&Bs[kk][tx * 8];
            *(float4*)&b[4] = *(const float4*)&Bs[kk][tx * 8 + 4];
#pragma unroll
            for (int i = 0; i < 8; ++i)
#pragma unroll
                for (int j = 0; j < 8; ++j) acc[i][j] += a[i] * b[j];
        }
        __syncthreads();
    }
#pragma unroll
    for (int i = 0; i < 8; ++i) {
        int r = ty * 8 + i;
        int p = sp[r];
        if (p < 0) continue;
        int t = p >> 1;
        float w = sw[r];
        float* dst = C + (size_t)t * H + blockIdx.y * 128 + tx * 8;
#pragma unroll
        for (int j = 0; j < 8; ++j) atomicAdd(dst + j, w * acc[i][j]);
    }
}

// ---------------------------------------------------------------------------
extern "C" void kernel_launch(void* const* d_in, const int* in_sizes, int n_in,
                              void* d_out, int out_size) {
    const float* x         = (const float*)d_in[0];
    const float* ln1_g     = (const float*)d_in[1];
    const float* ln1_b     = (const float*)d_in[2];
    const float* attn_w    = (const float*)d_in[3];
    const float* ln2_g     = (const float*)d_in[4];
    const float* ln2_b     = (const float*)d_in[5];
    const float* gate_w    = (const float*)d_in[6];
    const float* gate_proj = (const float*)d_in[7];
    const float* up_proj   = (const float*)d_in[8];
    const float* down_proj = (const float*)d_in[9];
    float* out = (float*)d_out;

    zero_cnt_kernel<<<1, 32>>>();
    ln_kernel<<<TT, 256>>>(x, ln1_g, ln1_b);                          // g_tn = LN1(x)
    attn_gemm_kernel<<<dim3(TT / 128, H / 128), 256>>>(attn_w, x, out); // out = h
    ln_kernel<<<TT, 256>>>(out, ln2_g, ln2_b);                        // g_tn = LN2(h)
    gate_topk_kernel<<<TT / 8, 256>>>(gate_w);
    mlp1_kernel<<<dim3(TT / 128, INTER / 64, NE), 256>>>(gate_proj, up_proj);
    mlp2_kernel<<<dim3(TT / 128, H / 128, NE), 256>>>(down_proj, out);
}

// round 4
// speedup vs baseline: 4.4720x; 4.4720x over previous
#include <cuda_runtime.h>
#include <math.h>
#include <stdint.h>

#define H     1024
#define INTER 4096
#define NE    8
#define TT    8192
#define LNEPS 1e-5f
#define BK    32
#define LDS_  36                 // padded smem row stride (floats)
#define TILE_F (128 * LDS_)      // floats per 128-row tile
#define TILE_B (TILE_F * 4)      // 18432 bytes

// ---------------- scratch (static device globals) ---------------------------
__device__ float g_tn[(size_t)TT * H];           // LN outputs (fp32, later tf32-rounded)
__device__ float g_act[(size_t)TT * 2 * INTER];  // silu(g)*u per pair (tf32-rounded)
__device__ float g_o[(size_t)TT * 2 * H];        // per-pair weighted down-proj out
__device__ int   g_cnt[NE];
__device__ int   g_list[NE * TT];                // pair code p = token*2 + slot
__device__ float g_w[NE * TT];
__device__ float g_wg[(size_t)NE * INTER * H];   // rna-tf32 rounded weights
__device__ float g_wu[(size_t)NE * INTER * H];
__device__ float g_wd[(size_t)NE * H * INTER];

// ---------------- helpers ---------------------------------------------------
__device__ __forceinline__ uint32_t smem_u32(const void* p) {
    uint32_t a;
    asm("{ .reg .u64 t; cvta.to.shared.u64 t, %1; cvt.u32.u64 %0, t; }" : "=r"(a) : "l"(p));
    return a;
}
__device__ __forceinline__ float tf32r(float x) {
    uint32_t u;
    asm("cvt.rna.tf32.f32 %0, %1;" : "=r"(u) : "f"(x));
    return __uint_as_float(u);
}
__device__ __forceinline__ void cpasync16(uint32_t s, const void* g) {
    asm volatile("cp.async.cg.shared.global [%0], [%1], 16;" :: "r"(s), "l"(g));
}
#define CP_COMMIT() asm volatile("cp.async.commit_group;" ::: "memory")
#define CP_WAIT(n)  asm volatile("cp.async.wait_group %0;" :: "n"(n) : "memory")

__device__ __forceinline__ void mma8(float* c, const float* a, const float* b) {
    asm volatile(
        "mma.sync.aligned.m16n8k8.row.col.f32.tf32.tf32.f32 "
        "{%0,%1,%2,%3}, {%4,%5,%6,%7}, {%8,%9}, {%0,%1,%2,%3};"
        : "+f"(c[0]), "+f"(c[1]), "+f"(c[2]), "+f"(c[3])
        : "r"(__float_as_uint(a[0])), "r"(__float_as_uint(a[1])),
          "r"(__float_as_uint(a[2])), "r"(__float_as_uint(a[3])),
          "r"(__float_as_uint(b[0])), "r"(__float_as_uint(b[1])));
}

// ---------------------------------------------------------------------------
__global__ void zero_cnt_kernel() {
    if (threadIdx.x < NE) g_cnt[threadIdx.x] = 0;
}

__global__ void __launch_bounds__(256) round_wg_k(const float4* __restrict__ s, int n4) {
    int i = blockIdx.x * blockDim.x + threadIdx.x;
    if (i < n4) {
        float4 v = s[i];
        v.x = tf32r(v.x); v.y = tf32r(v.y); v.z = tf32r(v.z); v.w = tf32r(v.w);
        ((float4*)g_wg)[i] = v;
    }
}
__global__ void __launch_bounds__(256) round_wu_k(const float4* __restrict__ s, int n4) {
    int i = blockIdx.x * blockDim.x + threadIdx.x;
    if (i < n4) {
        float4 v = s[i];
        v.x = tf32r(v.x); v.y = tf32r(v.y); v.z = tf32r(v.z); v.w = tf32r(v.w);
        ((float4*)g_wu)[i] = v;
    }
}
__global__ void __launch_bounds__(256) round_wd_k(const float4* __restrict__ s, int n4) {
    int i = blockIdx.x * blockDim.x + threadIdx.x;
    if (i < n4) {
        float4 v = s[i];
        v.x = tf32r(v.x); v.y = tf32r(v.y); v.z = tf32r(v.z); v.w = tf32r(v.w);
        ((float4*)g_wd)[i] = v;
    }
}
__global__ void __launch_bounds__(256) round_tn_k(int n4) {
    int i = blockIdx.x * blockDim.x + threadIdx.x;
    if (i < n4) {
        float4 v = ((float4*)g_tn)[i];
        v.x = tf32r(v.x); v.y = tf32r(v.y); v.z = tf32r(v.z); v.w = tf32r(v.w);
        ((float4*)g_tn)[i] = v;
    }
}

__global__ void __launch_bounds__(256) ln_kernel(const float* __restrict__ src,
                                                 const float* __restrict__ gamma,
                                                 const float* __restrict__ beta) {
    int row = blockIdx.x;
    int tid = threadIdx.x;
    const float4 xv = ((const float4*)(src + (size_t)row * H))[tid];
    float s = xv.x + xv.y + xv.z + xv.w;
    float q = xv.x * xv.x + xv.y * xv.y + xv.z * xv.z + xv.w * xv.w;
#pragma unroll
    for (int o = 16; o; o >>= 1) {
        s += __shfl_xor_sync(0xffffffffu, s, o);
        q += __shfl_xor_sync(0xffffffffu, q, o);
    }
    __shared__ float ss[8], sq[8];
    __shared__ float sm_, sr_;
    int w = tid >> 5;
    if ((tid & 31) == 0) { ss[w] = s; sq[w] = q; }
    __syncthreads();
    if (tid == 0) {
        float S = 0.f, Q = 0.f;
#pragma unroll
        for (int i = 0; i < 8; ++i) { S += ss[i]; Q += sq[i]; }
        float m = S * (1.0f / H);
        float v = Q * (1.0f / H) - m * m;
        sm_ = m;
        sr_ = rsqrtf(v + LNEPS);
    }
    __syncthreads();
    float m = sm_, r = sr_;
    const float4 gv = ((const float4*)gamma)[tid];
    const float4 bv = ((const float4*)beta)[tid];
    float4 o;
    o.x = (xv.x - m) * r * gv.x + bv.x;
    o.y = (xv.y - m) * r * gv.y + bv.y;
    o.z = (xv.z - m) * r * gv.z + bv.z;
    o.w = (xv.w - m) * r * gv.w + bv.w;
    ((float4*)(g_tn + (size_t)row * H))[tid] = o;
}

__global__ void __launch_bounds__(256) gate_topk_kernel(const float* __restrict__ gw) {
    int t = (blockIdx.x * blockDim.x + threadIdx.x) >> 5;
    int lane = threadIdx.x & 31;
    if (t >= TT) return;
    const float* trow = g_tn + (size_t)t * H;
    float lg[NE];
#pragma unroll
    for (int e = 0; e < NE; ++e) {
        float s = 0.f;
        for (int j = lane; j < H; j += 32) s += trow[j] * gw[e * H + j];
#pragma unroll
        for (int o = 16; o; o >>= 1) s += __shfl_xor_sync(0xffffffffu, s, o);
        lg[e] = s;
    }
    if (lane == 0) {
        float v0 = -INFINITY; int i0 = 0;
#pragma unroll
        for (int e = 0; e < NE; ++e) if (lg[e] > v0) { v0 = lg[e]; i0 = e; }
        float v1 = -INFINITY; int i1 = 0;
#pragma unroll
        for (int e = 0; e < NE; ++e) if (e != i0 && lg[e] > v1) { v1 = lg[e]; i1 = e; }
        float ex = expf(v1 - v0);
        float w0 = 1.0f / (1.0f + ex);
        float w1 = ex / (1.0f + ex);
        int p0 = atomicAdd(&g_cnt[i0], 1);
        g_list[i0 * TT + p0] = t * 2 + 0;
        g_w[i0 * TT + p0] = w0;
        int p1 = atomicAdd(&g_cnt[i1], 1);
        g_list[i1 * TT + p1] = t * 2 + 1;
        g_w[i1 * TT + p1] = w1;
    }
}

extern __shared__ float smf[];

// ---------------------------------------------------------------------------
// attn: C = X + tn @ W^T via 3xTF32 split (hi/lo), full-fp32-accurate.
__global__ void __launch_bounds__(256) attn3_tc(const float* __restrict__ W,
                                                const float* __restrict__ X,
                                                float* __restrict__ C) {
    float* Ah = smf;
    float* Al = Ah + TILE_F;
    float* Bh = Al + TILE_F;
    float* Bl = Bh + TILE_F;
    int tid = threadIdx.x;
    int bm = blockIdx.x, bn = blockIdx.y;
    int wid = tid >> 5, lane = tid & 31;
    int wm = (wid >> 2) * 64, wn = (wid & 3) * 32;
    int g = lane >> 2, tc = lane & 3;
    int lr = tid >> 3, lc = (tid & 7) * 4;
    const float* Asrc = g_tn + (size_t)(bm * 128) * H + lc;
    const float* Bsrc = W + (size_t)(bn * 128) * H + lc;
    float acc[4][4][4] = {};
    for (int k0 = 0; k0 < H; k0 += BK) {
        __syncthreads();
#pragma unroll
        for (int i = 0; i < 4; ++i) {
            int r = lr + 32 * i;
            float4 av = *(const float4*)(Asrc + (size_t)r * H + k0);
            float4 hv, lv;
            hv.x = tf32r(av.x); lv.x = av.x - hv.x;
            hv.y = tf32r(av.y); lv.y = av.y - hv.y;
            hv.z = tf32r(av.z); lv.z = av.z - hv.z;
            hv.w = tf32r(av.w); lv.w = av.w - hv.w;
            *(float4*)(Ah + r * LDS_ + lc) = hv;
            *(float4*)(Al + r * LDS_ + lc) = lv;
            float4 bv = *(const float4*)(Bsrc + (size_t)r * H + k0);
            float4 bh, bl;
            bh.x = tf32r(bv.x); bl.x = bv.x - bh.x;
            bh.y = tf32r(bv.y); bl.y = bv.y - bh.y;
            bh.z = tf32r(bv.z); bl.z = bv.z - bh.z;
            bh.w = tf32r(bv.w); bl.w = bv.w - bh.w;
            *(float4*)(Bh + r * LDS_ + lc) = bh;
            *(float4*)(Bl + r * LDS_ + lc) = bl;
        }
        __syncthreads();
#pragma unroll
        for (int ks = 0; ks < 4; ++ks) {
            int k = ks * 8 + tc;
            float ah[4][4], al[4][4];
#pragma unroll
            for (int mt = 0; mt < 4; ++mt) {
                int r0 = wm + mt * 16 + g;
                ah[mt][0] = Ah[r0 * LDS_ + k];       ah[mt][1] = Ah[(r0 + 8) * LDS_ + k];
                ah[mt][2] = Ah[r0 * LDS_ + k + 4];   ah[mt][3] = Ah[(r0 + 8) * LDS_ + k + 4];
                al[mt][0] = Al[r0 * LDS_ + k];       al[mt][1] = Al[(r0 + 8) * LDS_ + k];
                al[mt][2] = Al[r0 * LDS_ + k + 4];   al[mt][3] = Al[(r0 + 8) * LDS_ + k + 4];
            }
#pragma unroll
            for (int nt = 0; nt < 4; ++nt) {
                int nr = wn + nt * 8 + g;
                float bh2[2], bl2[2];
                bh2[0] = Bh[nr * LDS_ + k]; bh2[1] = Bh[nr * LDS_ + k + 4];
                bl2[0] = Bl[nr * LDS_ + k]; bl2[1] = Bl[nr * LDS_ + k + 4];
#pragma unroll
                for (int mt = 0; mt < 4; ++mt) {
                    mma8(acc[mt][nt], al[mt], bh2);
                    mma8(acc[mt][nt], ah[mt], bl2);
                    mma8(acc[mt][nt], ah[mt], bh2);
                }
            }
        }
    }
#pragma unroll
    for (int mt = 0; mt < 4; ++mt) {
        int row0 = bm * 128 + wm + mt * 16 + g;
#pragma unroll
        for (int nt = 0; nt < 4; ++nt) {
            int col = bn * 128 + wn + nt * 8 + 2 * tc;
            float2 x0 = *(const float2*)(X + (size_t)row0 * H + col);
            float2 o0 = { x0.x + acc[mt][nt][0], x0.y + acc[mt][nt][1] };
            *(float2*)(C + (size_t)row0 * H + col) = o0;
            float2 x1 = *(const float2*)(X + (size_t)(row0 + 8) * H + col);
            float2 o1 = { x1.x + acc[mt][nt][2], x1.y + acc[mt][nt][3] };
            *(float2*)(C + (size_t)(row0 + 8) * H + col) = o1;
        }
    }
}

// ---------------------------------------------------------------------------
// mlp1: gathered A (tf32-rounded tn) x [gate | up] weights, silu(g)*u -> g_act.
// NOTE: g_wg/g_wu referenced DEVICE-SIDE (passing __device__ symbols as host
// kernel args silently binds the host shadow on ATS systems — R3 bug).
__global__ void __launch_bounds__(256) mlp1_tc() {
    int e = blockIdx.z;
    int cnt = g_cnt[e];
    int bm = blockIdx.x;
    if (bm * 128 >= cnt) return;
    int ib = blockIdx.y;
    __shared__ int sp[128];
    int tid = threadIdx.x;
    if (tid < 128) {
        int r = bm * 128 + tid;
        sp[tid] = (r < cnt) ? g_list[e * TT + r] : -1;
    }
    __syncthreads();
    int wid = tid >> 5, lane = tid & 31;
    int wm = (wid >> 2) * 64, wn = (wid & 3) * 32;
    int g = lane >> 2, tc = lane & 3;
    int lr = tid >> 3, lc = (tid & 7) * 4;
    const float* asrc[4];
#pragma unroll
    for (int i = 0; i < 4; ++i) {
        int p = sp[lr + 32 * i];
        int t = (p < 0) ? 0 : (p >> 1);
        asrc[i] = g_tn + (size_t)t * H + lc;
    }
    const float* bg0 = g_wg + ((size_t)e * INTER + ib * 128) * H + lc;
    const float* bu0 = g_wu + ((size_t)e * INTER + ib * 128) * H + lc;
    uint32_t smb = smem_u32(smf);
    float accg[4][4][4] = {}, accu[4][4][4] = {};
    {
        uint32_t base = smb;
#pragma unroll
        for (int i = 0; i < 4; ++i) {
            int r = lr + 32 * i;
            uint32_t d = base + (uint32_t)(r * LDS_ + lc) * 4;
            cpasync16(d, asrc[i]);
            cpasync16(d + TILE_B, bg0 + (size_t)r * H);
            cpasync16(d + 2 * TILE_B, bu0 + (size_t)r * H);
        }
        CP_COMMIT();
    }
    const int NCH = H / BK;
    for (int c = 0; c < NCH; ++c) {
        if (c + 1 < NCH) {
            uint32_t base = smb + ((c + 1) & 1) * (3 * TILE_B);
            int k0 = (c + 1) * BK;
#pragma unroll
            for (int i = 0; i < 4; ++i) {
                int r = lr + 32 * i;
                uint32_t d = base + (uint32_t)(r * LDS_ + lc) * 4;
                cpasync16(d, asrc[i] + k0);
                cpasync16(d + TILE_B, bg0 + (size_t)r * H + k0);
                cpasync16(d + 2 * TILE_B, bu0 + (size_t)r * H + k0);
            }
            CP_COMMIT();
            CP_WAIT(1);
        } else {
            CP_WAIT(0);
        }
        __syncthreads();
        const float* A = smf + (c & 1) * (3 * TILE_F);
        const float* Bg = A + TILE_F;
        const float* Bu = Bg + TILE_F;
#pragma unroll
        for (int ks = 0; ks < 4; ++ks) {
            int k = ks * 8 + tc;
            float a[4][4];
#pragma unroll
            for (int mt = 0; mt < 4; ++mt) {
                int r0 = wm + mt * 16 + g;
                a[mt][0] = A[r0 * LDS_ + k];       a[mt][1] = A[(r0 + 8) * LDS_ + k];
                a[mt][2] = A[r0 * LDS_ + k + 4];   a[mt][3] = A[(r0 + 8) * LDS_ + k + 4];
            }
#pragma unroll
            for (int nt = 0; nt < 4; ++nt) {
                int nr = wn + nt * 8 + g;
                float b[2];
                b[0] = Bg[nr * LDS_ + k]; b[1] = Bg[nr * LDS_ + k + 4];
#pragma unroll
                for (int mt = 0; mt < 4; ++mt) mma8(accg[mt][nt], a[mt], b);
                b[0] = Bu[nr * LDS_ + k]; b[1] = Bu[nr * LDS_ + k + 4];
#pragma unroll
                for (int mt = 0; mt < 4; ++mt) mma8(accu[mt][nt], a[mt], b);
            }
        }
        __syncthreads();
    }
#pragma unroll
    for (int mt = 0; mt < 4; ++mt) {
        int rl0 = wm + mt * 16 + g;
        int p0 = sp[rl0], p1 = sp[rl0 + 8];
#pragma unroll
        for (int nt = 0; nt < 4; ++nt) {
            int col = ib * 128 + wn + nt * 8 + 2 * tc;
            if (p0 >= 0) {
                float g0 = accg[mt][nt][0], u0 = accu[mt][nt][0];
                float g1 = accg[mt][nt][1], u1 = accu[mt][nt][1];
                float2 v;
                v.x = tf32r(g0 / (1.f + expf(-g0)) * u0);
                v.y = tf32r(g1 / (1.f + expf(-g1)) * u1);
                *(float2*)(g_act + (size_t)p0 * INTER + col) = v;
            }
            if (p1 >= 0) {
                float g2 = accg[mt][nt][2], u2 = accu[mt][nt][2];
                float g3 = accg[mt][nt][3], u3 = accu[mt][nt][3];
                float2 v;
                v.x = tf32r(g2 / (1.f + expf(-g2)) * u2);
                v.y = tf32r(g3 / (1.f + expf(-g3)) * u3);
                *(float2*)(g_act + (size_t)p1 * INTER + col) = v;
            }
        }
    }
}

// ---------------------------------------------------------------------------
// mlp2: gathered A (g_act) x down weights, scale by combine weight -> g_o.
__global__ void __launch_bounds__(256) mlp2_tc() {
    int e = blockIdx.z;
    int cnt = g_cnt[e];
    int bm = blockIdx.x;
    if (bm * 128 >= cnt) return;
    int bn = blockIdx.y;
    __shared__ int sp[128];
    __shared__ float sw[128];
    int tid = threadIdx.x;
    if (tid < 128) {
        int r = bm * 128 + tid;
        int valid = (r < cnt);
        sp[tid] = valid ? g_list[e * TT + r] : -1;
        sw[tid] = valid ? g_w[e * TT + r] : 0.f;
    }
    __syncthreads();
    int wid = tid >> 5, lane = tid & 31;
    int wm = (wid >> 2) * 64, wn = (wid & 3) * 32;
    int g = lane >> 2, tc = lane & 3;
    int lr = tid >> 3, lc = (tid & 7) * 4;
    const float* asrc[4];
#pragma unroll
    for (int i = 0; i < 4; ++i) {
        int p = sp[lr + 32 * i];
        int pp = (p < 0) ? 0 : p;
        asrc[i] = g_act + (size_t)pp * INTER + lc;
    }
    const float* b0 = g_wd + ((size_t)e * H + bn * 128) * INTER + lc;
    uint32_t smb = smem_u32(smf);
    float acc[4][4][4] = {};
    {
#pragma unroll
        for (int i = 0; i < 4; ++i) {
            int r = lr + 32 * i;
            uint32_t d = smb + (uint32_t)(r * LDS_ + lc) * 4;
            cpasync16(d, asrc[i]);
            cpasync16(d + TILE_B, b0 + (size_t)r * INTER);
        }
        CP_COMMIT();
    }
    const int NCH = INTER / BK;  // 128
    for (int c = 0; c < NCH; ++c) {
        if (c + 1 < NCH) {
            uint32_t base = smb + ((c + 1) & 1) * (2 * TILE_B);
            int k0 = (c + 1) * BK;
#pragma unroll
            for (int i = 0; i < 4; ++i) {
                int r = lr + 32 * i;
                uint32_t d = base + (uint32_t)(r * LDS_ + lc) * 4;
                cpasync16(d, asrc[i] + k0);
                cpasync16(d + TILE_B, b0 + (size_t)r * INTER + k0);
            }
            CP_COMMIT();
            CP_WAIT(1);
        } else {
            CP_WAIT(0);
        }
        __syncthreads();
        const float* A = smf + (c & 1) * (2 * TILE_F);
        const float* B = A + TILE_F;
#pragma unroll
        for (int ks = 0; ks < 4; ++ks) {
            int k = ks * 8 + tc;
            float a[4][4];
#pragma unroll
            for (int mt = 0; mt < 4; ++mt) {
                int r0 = wm + mt * 16 + g;
                a[mt][0] = A[r0 * LDS_ + k];       a[mt][1] = A[(r0 + 8) * LDS_ + k];
                a[mt][2] = A[r0 * LDS_ + k + 4];   a[mt][3] = A[(r0 + 8) * LDS_ + k + 4];
            }
#pragma unroll
            for (int nt = 0; nt < 4; ++nt) {
                int nr = wn + nt * 8 + g;
                float b[2];
                b[0] = B[nr * LDS_ + k]; b[1] = B[nr * LDS_ + k + 4];
#pragma unroll
                for (int mt = 0; mt < 4; ++mt) mma8(acc[mt][nt], a[mt], b);
            }
        }
        __syncthreads();
    }
#pragma unroll
    for (int mt = 0; mt < 4; ++mt) {
        int rl0 = wm + mt * 16 + g;
        int p0 = sp[rl0], p1 = sp[rl0 + 8];
        float w0 = sw[rl0], w1 = sw[rl0 + 8];
#pragma unroll
        for (int nt = 0; nt < 4; ++nt) {
            int col = bn * 128 + wn + nt * 8 + 2 * tc;
            if (p0 >= 0) {
                float2 v = { w0 * acc[mt][nt][0], w0 * acc[mt][nt][1] };
                *(float2*)(g_o + (size_t)p0 * H + col) = v;
            }
            if (p1 >= 0) {
                float2 v = { w1 * acc[mt][nt][2], w1 * acc[mt][nt][3] };
                *(float2*)(g_o + (size_t)p1 * H + col) = v;
            }
        }
    }
}

// out[t] += g_o[2t] + g_o[2t+1]
__global__ void __launch_bounds__(256) combine_kernel(float* __restrict__ C) {
    int v = blockIdx.x * blockDim.x + threadIdx.x;
    int t = v >> 8;
    int c = v & 255;
    const float4* go = (const float4*)g_o;
    float4 a = go[(size_t)(2 * t) * 256 + c];
    float4 b = go[(size_t)(2 * t) * 256 + 256 + c];
    float4* out = (float4*)C;
    float4 o = out[v];
    o.x += a.x + b.x; o.y += a.y + b.y; o.z += a.z + b.z; o.w += a.w + b.w;
    out[v] = o;
}

// ---------------------------------------------------------------------------
extern "C" void kernel_launch(void* const* d_in, const int* in_sizes, int n_in,
                              void* d_out, int out_size) {
    const float* x         = (const float*)d_in[0];
    const float* ln1_g     = (const float*)d_in[1];
    const float* ln1_b     = (const float*)d_in[2];
    const float* attn_w    = (const float*)d_in[3];
    const float* ln2_g     = (const float*)d_in[4];
    const float* ln2_b     = (const float*)d_in[5];
    const float* gate_w    = (const float*)d_in[6];
    const float* gate_proj = (const float*)d_in[7];
    const float* up_proj   = (const float*)d_in[8];
    const float* down_proj = (const float*)d_in[9];
    float* out = (float*)d_out;

    cudaFuncSetAttribute(attn3_tc, cudaFuncAttributeMaxDynamicSharedMemorySize, 4 * TILE_B);
    cudaFuncSetAttribute(mlp1_tc,  cudaFuncAttributeMaxDynamicSharedMemorySize, 6 * TILE_B);
    cudaFuncSetAttribute(mlp2_tc,  cudaFuncAttributeMaxDynamicSharedMemorySize, 4 * TILE_B);

    const int n4w = NE * INTER * H / 4;  // 8388608

    zero_cnt_kernel<<<1, 32>>>();
    round_wg_k<<<n4w / 256, 256>>>((const float4*)gate_proj, n4w);
    round_wu_k<<<n4w / 256, 256>>>((const float4*)up_proj, n4w);
    round_wd_k<<<n4w / 256, 256>>>((const float4*)down_proj, n4w);

    ln_kernel<<<TT, 256>>>(x, ln1_g, ln1_b);                                  // g_tn = LN1(x), fp32
    attn3_tc<<<dim3(TT / 128, H / 128), 256, 4 * TILE_B>>>(attn_w, x, out);   // out = h (3xTF32)
    ln_kernel<<<TT, 256>>>(out, ln2_g, ln2_b);                                // g_tn = LN2(h), fp32
    gate_topk_kernel<<<TT / 8, 256>>>(gate_w);                                // fp32 gating
    round_tn_k<<<(TT * H / 4) / 256, 256>>>(TT * H / 4);                      // g_tn -> rna tf32
    mlp1_tc<<<dim3(TT / 128, INTER / 128, NE), 256, 6 * TILE_B>>>();
    mlp2_tc<<<dim3(TT / 128, H / 128, NE), 256, 4 * TILE_B>>>();
    combine_kernel<<<(TT * H / 4) / 256, 256>>>(out);
}

// round 5
// speedup vs baseline: 7.9209x; 1.7712x over previous
#include <cuda_runtime.h>
#include <cuda_bf16.h>
#include <math.h>
#include <stdint.h>

#define H     1024
#define INTER 4096
#define NE    8
#define TT    8192
#define LNEPS 1e-5f

// attn (tf32 3x) tiling constants
#define BK    32
#define LDS_  36
#define TILE_F (128 * LDS_)
#define TILE_B (TILE_F * 4)

// bf16 MoE tiling: BK2=64, row stride 72 bf16 (144B), tile 128 rows
#define BK2    64
#define RS2    72                    // bf16 elements per smem row (64 + 8 pad)
#define TB2    (128 * RS2 * 2)       // 18432 bytes per tile
#define STG2   (2 * TB2)             // A + B per stage
#define SMEM2  (2 * STG2)            // 73728, two stages

// ---------------- scratch (static device globals) ---------------------------
__device__ float g_tn[(size_t)TT * H];                  // LN outputs fp32 (gate + attn)
__device__ __nv_bfloat16 g_tnh[(size_t)TT * H];         // LN2 out bf16 (mlp1 A)
__device__ __nv_bfloat16 g_acth[(size_t)TT * 2 * INTER];// silu(g)*u bf16 per pair
__device__ float g_o[(size_t)TT * 2 * H];               // per-pair weighted down out
__device__ int   g_cnt[NE];
__device__ int   g_list[NE * TT];
__device__ float g_w[NE * TT];
__device__ __nv_bfloat16 g_wgh[(size_t)NE * INTER * H]; // bf16 weight copies
__device__ __nv_bfloat16 g_wuh[(size_t)NE * INTER * H];
__device__ __nv_bfloat16 g_wdh[(size_t)NE * H * INTER];

// ---------------- helpers ---------------------------------------------------
__device__ __forceinline__ uint32_t smem_u32(const void* p) {
    uint32_t a;
    asm("{ .reg .u64 t; cvta.to.shared.u64 t, %1; cvt.u32.u64 %0, t; }" : "=r"(a) : "l"(p));
    return a;
}
__device__ __forceinline__ float tf32r(float x) {
    uint32_t u;
    asm("cvt.rna.tf32.f32 %0, %1;" : "=r"(u) : "f"(x));
    return __uint_as_float(u);
}
__device__ __forceinline__ uint32_t pkbf(float lo, float hi) {
    uint32_t r;
    asm("cvt.rn.bf16x2.f32 %0, %1, %2;" : "=r"(r) : "f"(hi), "f"(lo));
    return r;
}
__device__ __forceinline__ void cpasync16(uint32_t s, const void* g) {
    asm volatile("cp.async.cg.shared.global [%0], [%1], 16;" :: "r"(s), "l"(g));
}
#define CP_COMMIT() asm volatile("cp.async.commit_group;" ::: "memory")
#define CP_WAIT(n)  asm volatile("cp.async.wait_group %0;" :: "n"(n) : "memory")

__device__ __forceinline__ void mma8(float* c, const float* a, const float* b) {
    asm volatile(
        "mma.sync.aligned.m16n8k8.row.col.f32.tf32.tf32.f32 "
        "{%0,%1,%2,%3}, {%4,%5,%6,%7}, {%8,%9}, {%0,%1,%2,%3};"
        : "+f"(c[0]), "+f"(c[1]), "+f"(c[2]), "+f"(c[3])
        : "r"(__float_as_uint(a[0])), "r"(__float_as_uint(a[1])),
          "r"(__float_as_uint(a[2])), "r"(__float_as_uint(a[3])),
          "r"(__float_as_uint(b[0])), "r"(__float_as_uint(b[1])));
}
__device__ __forceinline__ void mma16(float* c, const uint32_t* a, const uint32_t* b) {
    asm volatile(
        "mma.sync.aligned.m16n8k16.row.col.f32.bf16.bf16.f32 "
        "{%0,%1,%2,%3}, {%4,%5,%6,%7}, {%8,%9}, {%0,%1,%2,%3};"
        : "+f"(c[0]), "+f"(c[1]), "+f"(c[2]), "+f"(c[3])
        : "r"(a[0]), "r"(a[1]), "r"(a[2]), "r"(a[3]), "r"(b[0]), "r"(b[1]));
}

// ---------------------------------------------------------------------------
__global__ void zero_cnt_kernel() {
    if (threadIdx.x < NE) g_cnt[threadIdx.x] = 0;
}

// fp32 -> bf16 weight copies (which: 0=gate, 1=up, 2=down)
__global__ void __launch_bounds__(256) wconv_k(const float4* __restrict__ s, int n4, int which) {
    int i = blockIdx.x * blockDim.x + threadIdx.x;
    if (i >= n4) return;
    float4 v = s[i];
    uint2 o = { pkbf(v.x, v.y), pkbf(v.z, v.w) };
    __nv_bfloat16* dst = (which == 0) ? g_wgh : (which == 1) ? g_wuh : g_wdh;
    ((uint2*)dst)[i] = o;
}

__global__ void __launch_bounds__(256) ln_kernel(const float* __restrict__ src,
                                                 const float* __restrict__ gamma,
                                                 const float* __restrict__ beta,
                                                 int write_bf16) {
    int row = blockIdx.x;
    int tid = threadIdx.x;
    const float4 xv = ((const float4*)(src + (size_t)row * H))[tid];
    float s = xv.x + xv.y + xv.z + xv.w;
    float q = xv.x * xv.x + xv.y * xv.y + xv.z * xv.z + xv.w * xv.w;
#pragma unroll
    for (int o = 16; o; o >>= 1) {
        s += __shfl_xor_sync(0xffffffffu, s, o);
        q += __shfl_xor_sync(0xffffffffu, q, o);
    }
    __shared__ float ss[8], sq[8];
    __shared__ float sm_, sr_;
    int w = tid >> 5;
    if ((tid & 31) == 0) { ss[w] = s; sq[w] = q; }
    __syncthreads();
    if (tid == 0) {
        float S = 0.f, Q = 0.f;
#pragma unroll
        for (int i = 0; i < 8; ++i) { S += ss[i]; Q += sq[i]; }
        float m = S * (1.0f / H);
        float v = Q * (1.0f / H) - m * m;
        sm_ = m;
        sr_ = rsqrtf(v + LNEPS);
    }
    __syncthreads();
    float m = sm_, r = sr_;
    const float4 gv = ((const float4*)gamma)[tid];
    const float4 bv = ((const float4*)beta)[tid];
    float4 o;
    o.x = (xv.x - m) * r * gv.x + bv.x;
    o.y = (xv.y - m) * r * gv.y + bv.y;
    o.z = (xv.z - m) * r * gv.z + bv.z;
    o.w = (xv.w - m) * r * gv.w + bv.w;
    ((float4*)(g_tn + (size_t)row * H))[tid] = o;
    if (write_bf16) {
        uint2 p = { pkbf(o.x, o.y), pkbf(o.z, o.w) };
        ((uint2*)(g_tnh + (size_t)row * H))[tid] = p;
    }
}

__global__ void __launch_bounds__(256) gate_topk_kernel(const float* __restrict__ gw) {
    int t = (blockIdx.x * blockDim.x + threadIdx.x) >> 5;
    int lane = threadIdx.x & 31;
    if (t >= TT) return;
    const float* trow = g_tn + (size_t)t * H;
    float lg[NE];
#pragma unroll
    for (int e = 0; e < NE; ++e) {
        float s = 0.f;
        for (int j = lane; j < H; j += 32) s += trow[j] * gw[e * H + j];
#pragma unroll
        for (int o = 16; o; o >>= 1) s += __shfl_xor_sync(0xffffffffu, s, o);
        lg[e] = s;
    }
    if (lane == 0) {
        float v0 = -INFINITY; int i0 = 0;
#pragma unroll
        for (int e = 0; e < NE; ++e) if (lg[e] > v0) { v0 = lg[e]; i0 = e; }
        float v1 = -INFINITY; int i1 = 0;
#pragma unroll
        for (int e = 0; e < NE; ++e) if (e != i0 && lg[e] > v1) { v1 = lg[e]; i1 = e; }
        float ex = expf(v1 - v0);
        float w0 = 1.0f / (1.0f + ex);
        float w1 = ex / (1.0f + ex);
        int p0 = atomicAdd(&g_cnt[i0], 1);
        g_list[i0 * TT + p0] = t * 2 + 0;
        g_w[i0 * TT + p0] = w0;
        int p1 = atomicAdd(&g_cnt[i1], 1);
        g_list[i1 * TT + p1] = t * 2 + 1;
        g_w[i1 * TT + p1] = w1;
    }
}

extern __shared__ float smf[];

// ---------------------------------------------------------------------------
// attn: C = X + tn @ W^T via 3xTF32 split (hi/lo), fp32-accurate (protects top-k).
__global__ void __launch_bounds__(256) attn3_tc(const float* __restrict__ W,
                                                const float* __restrict__ X,
                                                float* __restrict__ C) {
    float* Ah = smf;
    float* Al = Ah + TILE_F;
    float* Bh = Al + TILE_F;
    float* Bl = Bh + TILE_F;
    int tid = threadIdx.x;
    int bm = blockIdx.x, bn = blockIdx.y;
    int wid = tid >> 5, lane = tid & 31;
    int wm = (wid >> 2) * 64, wn = (wid & 3) * 32;
    int g = lane >> 2, tc = lane & 3;
    int lr = tid >> 3, lc = (tid & 7) * 4;
    const float* Asrc = g_tn + (size_t)(bm * 128) * H + lc;
    const float* Bsrc = W + (size_t)(bn * 128) * H + lc;
    float acc[4][4][4] = {};
    for (int k0 = 0; k0 < H; k0 += BK) {
        __syncthreads();
#pragma unroll
        for (int i = 0; i < 4; ++i) {
            int r = lr + 32 * i;
            float4 av = *(const float4*)(Asrc + (size_t)r * H + k0);
            float4 hv, lv;
            hv.x = tf32r(av.x); lv.x = av.x - hv.x;
            hv.y = tf32r(av.y); lv.y = av.y - hv.y;
            hv.z = tf32r(av.z); lv.z = av.z - hv.z;
            hv.w = tf32r(av.w); lv.w = av.w - hv.w;
            *(float4*)(Ah + r * LDS_ + lc) = hv;
            *(float4*)(Al + r * LDS_ + lc) = lv;
            float4 bv = *(const float4*)(Bsrc + (size_t)r * H + k0);
            float4 bh, bl;
            bh.x = tf32r(bv.x); bl.x = bv.x - bh.x;
            bh.y = tf32r(bv.y); bl.y = bv.y - bh.y;
            bh.z = tf32r(bv.z); bl.z = bv.z - bh.z;
            bh.w = tf32r(bv.w); bl.w = bv.w - bh.w;
            *(float4*)(Bh + r * LDS_ + lc) = bh;
            *(float4*)(Bl + r * LDS_ + lc) = bl;
        }
        __syncthreads();
#pragma unroll
        for (int ks = 0; ks < 4; ++ks) {
            int k = ks * 8 + tc;
            float ah[4][4], al[4][4];
#pragma unroll
            for (int mt = 0; mt < 4; ++mt) {
                int r0 = wm + mt * 16 + g;
                ah[mt][0] = Ah[r0 * LDS_ + k];       ah[mt][1] = Ah[(r0 + 8) * LDS_ + k];
                ah[mt][2] = Ah[r0 * LDS_ + k + 4];   ah[mt][3] = Ah[(r0 + 8) * LDS_ + k + 4];
                al[mt][0] = Al[r0 * LDS_ + k];       al[mt][1] = Al[(r0 + 8) * LDS_ + k];
                al[mt][2] = Al[r0 * LDS_ + k + 4];   al[mt][3] = Al[(r0 + 8) * LDS_ + k + 4];
            }
#pragma unroll
            for (int nt = 0; nt < 4; ++nt) {
                int nr = wn + nt * 8 + g;
                float bh2[2], bl2[2];
                bh2[0] = Bh[nr * LDS_ + k]; bh2[1] = Bh[nr * LDS_ + k + 4];
                bl2[0] = Bl[nr * LDS_ + k]; bl2[1] = Bl[nr * LDS_ + k + 4];
#pragma unroll
                for (int mt = 0; mt < 4; ++mt) {
                    mma8(acc[mt][nt], al[mt], bh2);
                    mma8(acc[mt][nt], ah[mt], bl2);
                    mma8(acc[mt][nt], ah[mt], bh2);
                }
            }
        }
    }
#pragma unroll
    for (int mt = 0; mt < 4; ++mt) {
        int row0 = bm * 128 + wm + mt * 16 + g;
#pragma unroll
        for (int nt = 0; nt < 4; ++nt) {
            int col = bn * 128 + wn + nt * 8 + 2 * tc;
            float2 x0 = *(const float2*)(X + (size_t)row0 * H + col);
            float2 o0 = { x0.x + acc[mt][nt][0], x0.y + acc[mt][nt][1] };
            *(float2*)(C + (size_t)row0 * H + col) = o0;
            float2 x1 = *(const float2*)(X + (size_t)(row0 + 8) * H + col);
            float2 o1 = { x1.x + acc[mt][nt][2], x1.y + acc[mt][nt][3] };
            *(float2*)(C + (size_t)(row0 + 8) * H + col) = o1;
        }
    }
}

// ---------------------------------------------------------------------------
// mlp1 (bf16): tile 128 pairs x 64 inter cols, B = [64 gate rows ; 64 up rows].
// Each thread owns matching gate/up outputs -> fused silu. 2 CTAs/SM.
__global__ void __launch_bounds__(256, 2) mlp1_tc() {
    int e = blockIdx.z;
    int cnt = g_cnt[e];
    int bm = blockIdx.x;
    if (bm * 128 >= cnt) return;
    int ib = blockIdx.y;                 // inter block of 64
    __shared__ int sp[128];
    int tid = threadIdx.x;
    if (tid < 128) {
        int r = bm * 128 + tid;
        sp[tid] = (r < cnt) ? g_list[e * TT + r] : -1;
    }
    __syncthreads();
    int wid = tid >> 5, lane = tid & 31;
    int wm = (wid >> 2) * 64, wn = (wid & 3) * 16;
    int g = lane >> 2, tc = lane & 3;

    // loader mapping: 4 rows per thread (A and B), 16B chunk q
    int lr0 = tid >> 3, q = tid & 7;     // lr0: 0..31 base, rows lr0+32i
    const char* asrc[4];
    const char* bsrc[4];
#pragma unroll
    for (int i = 0; i < 4; ++i) {
        int r = lr0 + 32 * i;
        int p = sp[r];
        int t = (p < 0) ? 0 : (p >> 1);
        asrc[i] = (const char*)(g_tnh + (size_t)t * H) + q * 16;
        const __nv_bfloat16* wsrc = (r < 64)
            ? (g_wgh + ((size_t)e * INTER + ib * 64 + r) * H)
            : (g_wuh + ((size_t)e * INTER + ib * 64 + (r - 64)) * H);
        bsrc[i] = (const char*)wsrc + q * 16;
    }
    uint32_t smb = smem_u32(smf);
    uint32_t dofs = (uint32_t)(lr0 * 144 + q * 16);
    float accg[4][2][4] = {}, accu[4][2][4] = {};
    {
#pragma unroll
        for (int i = 0; i < 4; ++i) {
            uint32_t d = smb + dofs + i * (32 * 144);
            cpasync16(d, asrc[i]);
            cpasync16(d + TB2, bsrc[i]);
        }
        CP_COMMIT();
    }
    const int NCH = H / BK2;  // 16
    for (int c = 0; c < NCH; ++c) {
        if (c + 1 < NCH) {
            uint32_t base = smb + ((c + 1) & 1) * STG2;
            int kb = (c + 1) * BK2 * 2;  // byte advance in bf16 rows
#pragma unroll
            for (int i = 0; i < 4; ++i) {
                uint32_t d = base + dofs + i * (32 * 144);
                cpasync16(d, asrc[i] + kb);
                cpasync16(d + TB2, bsrc[i] + kb);
            }
            CP_COMMIT();
            CP_WAIT(1);
        } else {
            CP_WAIT(0);
        }
        __syncthreads();
        const uint32_t* A = (const uint32_t*)((const char*)smf + (c & 1) * STG2);
        const uint32_t* B = A + TB2 / 4;
#pragma unroll
        for (int ks = 0; ks < 4; ++ks) {
            uint32_t a[4][4];
#pragma unroll
            for (int mt = 0; mt < 4; ++mt) {
                int base = (wm + mt * 16 + g) * 36 + ks * 8 + tc;
                a[mt][0] = A[base];            a[mt][1] = A[base + 8 * 36];
                a[mt][2] = A[base + 4];        a[mt][3] = A[base + 8 * 36 + 4];
            }
#pragma unroll
            for (int nt = 0; nt < 2; ++nt) {
                int bb = (wn + nt * 8 + g) * 36 + ks * 8 + tc;
                uint32_t bg[2] = { B[bb], B[bb + 4] };
                uint32_t bu[2] = { B[bb + 64 * 36], B[bb + 64 * 36 + 4] };
#pragma unroll
                for (int mt = 0; mt < 4; ++mt) {
                    mma16(accg[mt][nt], a[mt], bg);
                    mma16(accu[mt][nt], a[mt], bu);
                }
            }
        }
        __syncthreads();
    }
#pragma unroll
    for (int mt = 0; mt < 4; ++mt) {
        int r0 = wm + mt * 16 + g;
        int p0 = sp[r0], p1 = sp[r0 + 8];
#pragma unroll
        for (int nt = 0; nt < 2; ++nt) {
            int col = ib * 64 + wn + nt * 8 + 2 * tc;
            if (p0 >= 0) {
                float g0 = accg[mt][nt][0], u0 = accu[mt][nt][0];
                float g1 = accg[mt][nt][1], u1 = accu[mt][nt][1];
                uint32_t v = pkbf(g0 / (1.f + expf(-g0)) * u0,
                                  g1 / (1.f + expf(-g1)) * u1);
                *(uint32_t*)(g_acth + (size_t)p0 * INTER + col) = v;
            }
            if (p1 >= 0) {
                float g2 = accg[mt][nt][2], u2 = accu[mt][nt][2];
                float g3 = accg[mt][nt][3], u3 = accu[mt][nt][3];
                uint32_t v = pkbf(g2 / (1.f + expf(-g2)) * u2,
                                  g3 / (1.f + expf(-g3)) * u3);
                *(uint32_t*)(g_acth + (size_t)p1 * INTER + col) = v;
            }
        }
    }
}

// ---------------------------------------------------------------------------
// mlp2 (bf16): tile 128 pairs x 128 H cols, K=INTER. w * D -> g_o (fp32).
__global__ void __launch_bounds__(256, 2) mlp2_tc() {
    int e = blockIdx.z;
    int cnt = g_cnt[e];
    int bm = blockIdx.x;
    if (bm * 128 >= cnt) return;
    int bn = blockIdx.y;
    __shared__ int sp[128];
    __shared__ float sw[128];
    int tid = threadIdx.x;
    if (tid < 128) {
        int r = bm * 128 + tid;
        int valid = (r < cnt);
        sp[tid] = valid ? g_list[e * TT + r] : -1;
        sw[tid] = valid ? g_w[e * TT + r] : 0.f;
    }
    __syncthreads();
    int wid = tid >> 5, lane = tid & 31;
    int wm = (wid >> 2) * 64, wn = (wid & 3) * 32;
    int g = lane >> 2, tc = lane & 3;

    int lr0 = tid >> 3, q = tid & 7;
    const char* asrc[4];
    const char* bsrc[4];
#pragma unroll
    for (int i = 0; i < 4; ++i) {
        int r = lr0 + 32 * i;
        int p = sp[r];
        int pp = (p < 0) ? 0 : p;
        asrc[i] = (const char*)(g_acth + (size_t)pp * INTER) + q * 16;
        bsrc[i] = (const char*)(g_wdh + ((size_t)e * H + bn * 128 + r) * INTER) + q * 16;
    }
    uint32_t smb = smem_u32(smf);
    uint32_t dofs = (uint32_t)(lr0 * 144 + q * 16);
    float acc[4][4][4] = {};
    {
#pragma unroll
        for (int i = 0; i < 4; ++i) {
            uint32_t d = smb + dofs + i * (32 * 144);
            cpasync16(d, asrc[i]);
            cpasync16(d + TB2, bsrc[i]);
        }
        CP_COMMIT();
    }
    const int NCH = INTER / BK2;  // 64
    for (int c = 0; c < NCH; ++c) {
        if (c + 1 < NCH) {
            uint32_t base = smb + ((c + 1) & 1) * STG2;
            int kb = (c + 1) * BK2 * 2;
#pragma unroll
            for (int i = 0; i < 4; ++i) {
                uint32_t d = base + dofs + i * (32 * 144);
                cpasync16(d, asrc[i] + kb);
                cpasync16(d + TB2, bsrc[i] + kb);
            }
            CP_COMMIT();
            CP_WAIT(1);
        } else {
            CP_WAIT(0);
        }
        __syncthreads();
        const uint32_t* A = (const uint32_t*)((const char*)smf + (c & 1) * STG2);
        const uint32_t* B = A + TB2 / 4;
#pragma unroll
        for (int ks = 0; ks < 4; ++ks) {
            uint32_t a[4][4];
#pragma unroll
            for (int mt = 0; mt < 4; ++mt) {
                int base = (wm + mt * 16 + g) * 36 + ks * 8 + tc;
                a[mt][0] = A[base];            a[mt][1] = A[base + 8 * 36];
                a[mt][2] = A[base + 4];        a[mt][3] = A[base + 8 * 36 + 4];
            }
#pragma unroll
            for (int nt = 0; nt < 4; ++nt) {
                int bb = (wn + nt * 8 + g) * 36 + ks * 8 + tc;
                uint32_t b[2] = { B[bb], B[bb + 4] };
#pragma unroll
                for (int mt = 0; mt < 4; ++mt) mma16(acc[mt][nt], a[mt], b);
            }
        }
        __syncthreads();
    }
#pragma unroll
    for (int mt = 0; mt < 4; ++mt) {
        int r0 = wm + mt * 16 + g;
        int p0 = sp[r0], p1 = sp[r0 + 8];
        float w0 = sw[r0], w1 = sw[r0 + 8];
#pragma unroll
        for (int nt = 0; nt < 4; ++nt) {
            int col = bn * 128 + wn + nt * 8 + 2 * tc;
            if (p0 >= 0) {
                float2 v = { w0 * acc[mt][nt][0], w0 * acc[mt][nt][1] };
                *(float2*)(g_o + (size_t)p0 * H + col) = v;
            }
            if (p1 >= 0) {
                float2 v = { w1 * acc[mt][nt][2], w1 * acc[mt][nt][3] };
                *(float2*)(g_o + (size_t)p1 * H + col) = v;
            }
        }
    }
}

// out[t] += g_o[2t] + g_o[2t+1]
__global__ void __launch_bounds__(256) combine_kernel(float* __restrict__ C) {
    int v = blockIdx.x * blockDim.x + threadIdx.x;
    int t = v >> 8;
    int c = v & 255;
    const float4* go = (const float4*)g_o;
    float4 a = go[(size_t)(2 * t) * 256 + c];
    float4 b = go[(size_t)(2 * t) * 256 + 256 + c];
    float4* out = (float4*)C;
    float4 o = out[v];
    o.x += a.x + b.x; o.y += a.y + b.y; o.z += a.z + b.z; o.w += a.w + b.w;
    out[v] = o;
}

// ---------------------------------------------------------------------------
extern "C" void kernel_launch(void* const* d_in, const int* in_sizes, int n_in,
                              void* d_out, int out_size) {
    const float* x         = (const float*)d_in[0];
    const float* ln1_g     = (const float*)d_in[1];
    const float* ln1_b     = (const float*)d_in[2];
    const float* attn_w    = (const float*)d_in[3];
    const float* ln2_g     = (const float*)d_in[4];
    const float* ln2_b     = (const float*)d_in[5];
    const float* gate_w    = (const float*)d_in[6];
    const float* gate_proj = (const float*)d_in[7];
    const float* up_proj   = (const float*)d_in[8];
    const float* down_proj = (const float*)d_in[9];
    float* out = (float*)d_out;

    cudaFuncSetAttribute(attn3_tc, cudaFuncAttributeMaxDynamicSharedMemorySize, 4 * TILE_B);
    cudaFuncSetAttribute(mlp1_tc,  cudaFuncAttributeMaxDynamicSharedMemorySize, SMEM2);
    cudaFuncSetAttribute(mlp2_tc,  cudaFuncAttributeMaxDynamicSharedMemorySize, SMEM2);

    const int n4w = NE * INTER * H / 4;  // 8388608

    zero_cnt_kernel<<<1, 32>>>();
    wconv_k<<<n4w / 256, 256>>>((const float4*)gate_proj, n4w, 0);
    wconv_k<<<n4w / 256, 256>>>((const float4*)up_proj,   n4w, 1);
    wconv_k<<<n4w / 256, 256>>>((const float4*)down_proj, n4w, 2);

    ln_kernel<<<TT, 256>>>(x, ln1_g, ln1_b, 0);                               // g_tn = LN1(x)
    attn3_tc<<<dim3(TT / 128, H / 128), 256, 4 * TILE_B>>>(attn_w, x, out);   // out = h
    ln_kernel<<<TT, 256>>>(out, ln2_g, ln2_b, 1);                             // g_tn fp32 + g_tnh bf16
    gate_topk_kernel<<<TT / 8, 256>>>(gate_w);                                // fp32 gating
    mlp1_tc<<<dim3(TT / 128, INTER / 64, NE), 256, SMEM2>>>();
    mlp2_tc<<<dim3(TT / 128, H / 128, NE), 256, SMEM2>>>();
    combine_kernel<<<(TT * H / 4) / 256, 256>>>(out);
}

// round 6
// speedup vs baseline: 9.0114x; 1.1377x over previous
#include <cuda_runtime.h>
#include <cuda_fp16.h>
#include <math.h>
#include <stdint.h>

#define H     1024
#define INTER 4096
#define NE    8
#define TT    8192
#define LNEPS 1e-5f

// fp16 tiling: 128-row tiles, 64-half K chunks, 144B padded rows
#define BK2    64
#define RB     144                   // bytes per smem row (64*2 + 16 pad)
#define TB2    (128 * RB)            // 18432 bytes per tile
#define STG2   (2 * TB2)             // A + B per stage = 36864
#define SMEM2  (3 * STG2)            // 110592 (3-stage)
#define SMEMA  (4 * TB2)             // attn: Ah, Al, Bh, Bl = 73728

// ---------------- scratch (static device globals) ---------------------------
__device__ float  g_tn[(size_t)TT * H];                  // LN outputs fp32
__device__ __half g_tnh[(size_t)TT * H];                 // LN2 out fp16
__device__ __half g_acth[(size_t)TT * 2 * INTER];        // silu(g)*u fp16 per pair
__device__ float  g_o[(size_t)TT * 2 * H];               // per-pair weighted down out
__device__ int    g_cnt[NE];
__device__ int    g_list[NE * TT];
__device__ float  g_w[NE * TT];
__device__ __half g_wgh[(size_t)NE * INTER * H];         // fp16 weight copies
__device__ __half g_wuh[(size_t)NE * INTER * H];
__device__ __half g_wdh[(size_t)NE * H * INTER];

// ---------------- helpers ---------------------------------------------------
__device__ __forceinline__ uint32_t smem_u32(const void* p) {
    uint32_t a;
    asm("{ .reg .u64 t; cvta.to.shared.u64 t, %1; cvt.u32.u64 %0, t; }" : "=r"(a) : "l"(p));
    return a;
}
__device__ __forceinline__ uint32_t pkhf(float lo, float hi) {
    uint32_t r;
    asm("cvt.rn.f16x2.f32 %0, %1, %2;" : "=r"(r) : "f"(hi), "f"(lo));
    return r;
}
__device__ __forceinline__ void cpasync16(uint32_t s, const void* g) {
    asm volatile("cp.async.cg.shared.global [%0], [%1], 16;" :: "r"(s), "l"(g));
}
#define CP_COMMIT() asm volatile("cp.async.commit_group;" ::: "memory")
#define CP_WAIT(n)  asm volatile("cp.async.wait_group %0;" :: "n"(n) : "memory")

__device__ __forceinline__ void ldsm4(uint32_t* r, uint32_t addr) {
    asm volatile("ldmatrix.sync.aligned.m8n8.x4.shared.b16 {%0,%1,%2,%3}, [%4];"
                 : "=r"(r[0]), "=r"(r[1]), "=r"(r[2]), "=r"(r[3]) : "r"(addr));
}
__device__ __forceinline__ void mma16f(float* c, const uint32_t* a, const uint32_t* b) {
    asm volatile(
        "mma.sync.aligned.m16n8k16.row.col.f32.f16.f16.f32 "
        "{%0,%1,%2,%3}, {%4,%5,%6,%7}, {%8,%9}, {%0,%1,%2,%3};"
        : "+f"(c[0]), "+f"(c[1]), "+f"(c[2]), "+f"(c[3])
        : "r"(a[0]), "r"(a[1]), "r"(a[2]), "r"(a[3]), "r"(b[0]), "r"(b[1]));
}

// ---------------------------------------------------------------------------
__global__ void zero_cnt_kernel() {
    if (threadIdx.x < NE) g_cnt[threadIdx.x] = 0;
}

// fp32 -> fp16 weight copies; blockIdx.y selects target (0=gate,1=up,2=down)
__global__ void __launch_bounds__(256) wconv_k(const float4* __restrict__ sg,
                                               const float4* __restrict__ su,
                                               const float4* __restrict__ sd, int n4) {
    int i = blockIdx.x * blockDim.x + threadIdx.x;
    if (i >= n4) return;
    int which = blockIdx.y;
    const float4* s = (which == 0) ? sg : (which == 1) ? su : sd;
    float4 v = s[i];
    uint2 o = { pkhf(v.x, v.y), pkhf(v.z, v.w) };
    __half* dst = (which == 0) ? g_wgh : (which == 1) ? g_wuh : g_wdh;
    ((uint2*)dst)[i] = o;
}

__global__ void __launch_bounds__(256) ln_kernel(const float* __restrict__ src,
                                                 const float* __restrict__ gamma,
                                                 const float* __restrict__ beta,
                                                 int write_fp16) {
    int row = blockIdx.x;
    int tid = threadIdx.x;
    const float4 xv = ((const float4*)(src + (size_t)row * H))[tid];
    float s = xv.x + xv.y + xv.z + xv.w;
    float q = xv.x * xv.x + xv.y * xv.y + xv.z * xv.z + xv.w * xv.w;
#pragma unroll
    for (int o = 16; o; o >>= 1) {
        s += __shfl_xor_sync(0xffffffffu, s, o);
        q += __shfl_xor_sync(0xffffffffu, q, o);
    }
    __shared__ float ss[8], sq[8];
    __shared__ float sm_, sr_;
    int w = tid >> 5;
    if ((tid & 31) == 0) { ss[w] = s; sq[w] = q; }
    __syncthreads();
    if (tid == 0) {
        float S = 0.f, Q = 0.f;
#pragma unroll
        for (int i = 0; i < 8; ++i) { S += ss[i]; Q += sq[i]; }
        float m = S * (1.0f / H);
        float v = Q * (1.0f / H) - m * m;
        sm_ = m;
        sr_ = rsqrtf(v + LNEPS);
    }
    __syncthreads();
    float m = sm_, r = sr_;
    const float4 gv = ((const float4*)gamma)[tid];
    const float4 bv = ((const float4*)beta)[tid];
    float4 o;
    o.x = (xv.x - m) * r * gv.x + bv.x;
    o.y = (xv.y - m) * r * gv.y + bv.y;
    o.z = (xv.z - m) * r * gv.z + bv.z;
    o.w = (xv.w - m) * r * gv.w + bv.w;
    ((float4*)(g_tn + (size_t)row * H))[tid] = o;
    if (write_fp16) {
        uint2 p = { pkhf(o.x, o.y), pkhf(o.z, o.w) };
        ((uint2*)(g_tnh + (size_t)row * H))[tid] = p;
    }
}

// gate + top2 + softmax + scatter; token row cached in registers
__global__ void __launch_bounds__(256) gate_topk_kernel(const float* __restrict__ gw) {
    int t = (blockIdx.x * blockDim.x + threadIdx.x) >> 5;
    int lane = threadIdx.x & 31;
    if (t >= TT) return;
    const float* trow = g_tn + (size_t)t * H;
    float tr[32];
#pragma unroll
    for (int i = 0; i < 32; ++i) tr[i] = trow[lane + 32 * i];
    float lg[NE];
#pragma unroll
    for (int e = 0; e < NE; ++e) {
        float s = 0.f;
        const float* gr = gw + e * H + lane;
#pragma unroll
        for (int i = 0; i < 32; ++i) s += tr[i] * gr[32 * i];
#pragma unroll
        for (int o = 16; o; o >>= 1) s += __shfl_xor_sync(0xffffffffu, s, o);
        lg[e] = s;
    }
    if (lane == 0) {
        float v0 = -INFINITY; int i0 = 0;
#pragma unroll
        for (int e = 0; e < NE; ++e) if (lg[e] > v0) { v0 = lg[e]; i0 = e; }
        float v1 = -INFINITY; int i1 = 0;
#pragma unroll
        for (int e = 0; e < NE; ++e) if (e != i0 && lg[e] > v1) { v1 = lg[e]; i1 = e; }
        float ex = expf(v1 - v0);
        float w0 = 1.0f / (1.0f + ex);
        float w1 = ex / (1.0f + ex);
        int p0 = atomicAdd(&g_cnt[i0], 1);
        g_list[i0 * TT + p0] = t * 2 + 0;
        g_w[i0 * TT + p0] = w0;
        int p1 = atomicAdd(&g_cnt[i1], 1);
        g_list[i1 * TT + p1] = t * 2 + 1;
        g_w[i1 * TT + p1] = w1;
    }
}

extern __shared__ float smf[];

// ---------------------------------------------------------------------------
// attn: C = X + tn @ W^T via fp16 2-term split (hh + hl + lh), fp32-accurate.
__global__ void __launch_bounds__(256) attn3_tc(const float* __restrict__ W,
                                                const float* __restrict__ X,
                                                float* __restrict__ C) {
    char* base = (char*)smf;
    uint32_t smb = smem_u32(smf);
    int tid = threadIdx.x;
    int bm = blockIdx.x, bn = blockIdx.y;
    int wid = tid >> 5, lane = tid & 31;
    int wm = (wid >> 2) * 64, wn = (wid & 3) * 32;

    int lr = tid >> 1, qh = tid & 1;     // loader: row 0..127, half 0/1
    const float* Asrc = g_tn + (size_t)(bm * 128 + lr) * H + qh * 32;
    const float* Bsrc = W + (size_t)(bn * 128 + lr) * H + qh * 32;
    char* Arow_h = base + lr * RB + qh * 64;            // 32 halfs = 64B
    char* Arow_l = Arow_h + TB2;
    char* Brow_h = Arow_h + 2 * TB2;
    char* Brow_l = Arow_h + 3 * TB2;

    uint32_t aoff[4];
#pragma unroll
    for (int mt = 0; mt < 4; ++mt)
        aoff[mt] = (uint32_t)((wm + mt * 16 + (lane & 15)) * RB + ((lane >> 4) & 1) * 16);
    uint32_t boff[2];
#pragma unroll
    for (int p = 0; p < 2; ++p)
        boff[p] = (uint32_t)((wn + (2 * p + ((lane >> 3) >> 1)) * 8 + (lane & 7)) * RB +
                             ((lane >> 3) & 1) * 16);

    float acc[4][4][4] = {};
    for (int k0 = 0; k0 < H; k0 += BK2) {
        __syncthreads();
#pragma unroll
        for (int i = 0; i < 8; ++i) {
            float4 av = *(const float4*)(Asrc + k0 + i * 4);
            __half hx = __float2half_rn(av.x), hy = __float2half_rn(av.y);
            __half hz = __float2half_rn(av.z), hw = __float2half_rn(av.w);
            uint2 hv = { pkhf(__half2float(hx), __half2float(hy)),
                         pkhf(__half2float(hz), __half2float(hw)) };
            uint2 lv = { pkhf(av.x - __half2float(hx), av.y - __half2float(hy)),
                         pkhf(av.z - __half2float(hz), av.w - __half2float(hw)) };
            *(uint2*)(Arow_h + i * 8) = hv;
            *(uint2*)(Arow_l + i * 8) = lv;
            float4 bv = *(const float4*)(Bsrc + k0 + i * 4);
            __half gx = __float2half_rn(bv.x), gy = __float2half_rn(bv.y);
            __half gz = __float2half_rn(bv.z), gw_ = __float2half_rn(bv.w);
            uint2 bhv = { pkhf(__half2float(gx), __half2float(gy)),
                          pkhf(__half2float(gz), __half2float(gw_)) };
            uint2 blv = { pkhf(bv.x - __half2float(gx), bv.y - __half2float(gy)),
                          pkhf(bv.z - __half2float(gz), bv.w - __half2float(gw_)) };
            *(uint2*)(Brow_h + i * 8) = bhv;
            *(uint2*)(Brow_l + i * 8) = blv;
        }
        __syncthreads();
#pragma unroll
        for (int ks = 0; ks < 4; ++ks) {
            uint32_t kb = ks * 32;
            uint32_t ah[4][4], al[4][4], bh[2][4], bl[2][4];
#pragma unroll
            for (int mt = 0; mt < 4; ++mt) {
                ldsm4(ah[mt], smb + aoff[mt] + kb);
                ldsm4(al[mt], smb + TB2 + aoff[mt] + kb);
            }
#pragma unroll
            for (int p = 0; p < 2; ++p) {
                ldsm4(bh[p], smb + 2 * TB2 + boff[p] + kb);
                ldsm4(bl[p], smb + 3 * TB2 + boff[p] + kb);
            }
#pragma unroll
            for (int nt = 0; nt < 4; ++nt) {
                const uint32_t* bhp = &bh[nt >> 1][(nt & 1) * 2];
                const uint32_t* blp = &bl[nt >> 1][(nt & 1) * 2];
#pragma unroll
                for (int mt = 0; mt < 4; ++mt) {
                    mma16f(acc[mt][nt], ah[mt], bhp);
                    mma16f(acc[mt][nt], ah[mt], blp);
                    mma16f(acc[mt][nt], al[mt], bhp);
                }
            }
        }
    }
    int g = lane >> 2, tc = lane & 3;
#pragma unroll
    for (int mt = 0; mt < 4; ++mt) {
        int row0 = bm * 128 + wm + mt * 16 + g;
#pragma unroll
        for (int nt = 0; nt < 4; ++nt) {
            int col = bn * 128 + wn + nt * 8 + 2 * tc;
            float2 x0 = *(const float2*)(X + (size_t)row0 * H + col);
            float2 o0 = { x0.x + acc[mt][nt][0], x0.y + acc[mt][nt][1] };
            *(float2*)(C + (size_t)row0 * H + col) = o0;
            float2 x1 = *(const float2*)(X + (size_t)(row0 + 8) * H + col);
            float2 o1 = { x1.x + acc[mt][nt][2], x1.y + acc[mt][nt][3] };
            *(float2*)(C + (size_t)(row0 + 8) * H + col) = o1;
        }
    }
}

// ---------------------------------------------------------------------------
// mlp1 (fp16): 128 pairs x 64 inter, B = [64 gate ; 64 up], 3-stage cp.async.
__global__ void __launch_bounds__(256, 2) mlp1_tc() {
    int e = blockIdx.z;
    int cnt = g_cnt[e];
    int bm = blockIdx.x;
    if (bm * 128 >= cnt) return;
    int ib = blockIdx.y;
    __shared__ int sp[128];
    int tid = threadIdx.x;
    if (tid < 128) {
        int r = bm * 128 + tid;
        sp[tid] = (r < cnt) ? g_list[e * TT + r] : -1;
    }
    __syncthreads();
    int wid = tid >> 5, lane = tid & 31;
    int wm = (wid >> 2) * 64, wn = (wid & 3) * 16;

    int lr0 = tid >> 3, q = tid & 7;
    const char* asrc[4];
    const char* bsrc[4];
#pragma unroll
    for (int i = 0; i < 4; ++i) {
        int r = lr0 + 32 * i;
        int p = sp[r];
        int t = (p < 0) ? 0 : (p >> 1);
        asrc[i] = (const char*)(g_tnh + (size_t)t * H) + q * 16;
        const __half* wsrc = (r < 64)
            ? (g_wgh + ((size_t)e * INTER + ib * 64 + r) * H)
            : (g_wuh + ((size_t)e * INTER + ib * 64 + (r - 64)) * H);
        bsrc[i] = (const char*)wsrc + q * 16;
    }
    uint32_t smb = smem_u32(smf);
    uint32_t dofs = (uint32_t)(lr0 * RB + q * 16);

    uint32_t aoff[4];
#pragma unroll
    for (int mt = 0; mt < 4; ++mt)
        aoff[mt] = (uint32_t)((wm + mt * 16 + (lane & 15)) * RB + ((lane >> 4) & 1) * 16);
    uint32_t boff = (uint32_t)((wn + ((lane >> 3) >> 1) * 8 + (lane & 7)) * RB +
                               ((lane >> 3) & 1) * 16);

    float accg[4][2][4] = {}, accu[4][2][4] = {};

#define LOAD1(st, c) do { \
    uint32_t bb_ = smb + (st) * STG2 + dofs; \
    int kb_ = (c) * 128; \
    _Pragma("unroll") \
    for (int i_ = 0; i_ < 4; ++i_) { \
        uint32_t d_ = bb_ + i_ * (32 * RB); \
        cpasync16(d_, asrc[i_] + kb_); \
        cpasync16(d_ + TB2, bsrc[i_] + kb_); \
    } } while (0)

    LOAD1(0, 0); CP_COMMIT();
    LOAD1(1, 1); CP_COMMIT();
    const int NCH = H / BK2;  // 16
    for (int c = 0; c < NCH; ++c) {
        if (c < NCH - 1) { CP_WAIT(1); } else { CP_WAIT(0); }
        __syncthreads();
        if (c + 2 < NCH) { LOAD1((c + 2) % 3, c + 2); CP_COMMIT(); }
        uint32_t sA = smb + (c % 3) * STG2;
        uint32_t sB = sA + TB2;
#pragma unroll
        for (int ks = 0; ks < 4; ++ks) {
            uint32_t kb = ks * 32;
            uint32_t a[4][4], bg[4], bu[4];
#pragma unroll
            for (int mt = 0; mt < 4; ++mt) ldsm4(a[mt], sA + aoff[mt] + kb);
            ldsm4(bg, sB + boff + kb);
            ldsm4(bu, sB + 64 * RB + boff + kb);
#pragma unroll
            for (int nt = 0; nt < 2; ++nt) {
#pragma unroll
                for (int mt = 0; mt < 4; ++mt) {
                    mma16f(accg[mt][nt], a[mt], &bg[nt * 2]);
                    mma16f(accu[mt][nt], a[mt], &bu[nt * 2]);
                }
            }
        }
    }
#undef LOAD1
    int g = lane >> 2, tc = lane & 3;
#pragma unroll
    for (int mt = 0; mt < 4; ++mt) {
        int r0 = wm + mt * 16 + g;
        int p0 = sp[r0], p1 = sp[r0 + 8];
#pragma unroll
        for (int nt = 0; nt < 2; ++nt) {
            int col = ib * 64 + wn + nt * 8 + 2 * tc;
            if (p0 >= 0) {
                float g0 = accg[mt][nt][0], u0 = accu[mt][nt][0];
                float g1 = accg[mt][nt][1], u1 = accu[mt][nt][1];
                uint32_t v = pkhf(g0 / (1.f + expf(-g0)) * u0,
                                  g1 / (1.f + expf(-g1)) * u1);
                *(uint32_t*)(g_acth + (size_t)p0 * INTER + col) = v;
            }
            if (p1 >= 0) {
                float g2 = accg[mt][nt][2], u2 = accu[mt][nt][2];
                float g3 = accg[mt][nt][3], u3 = accu[mt][nt][3];
                uint32_t v = pkhf(g2 / (1.f + expf(-g2)) * u2,
                                  g3 / (1.f + expf(-g3)) * u3);
                *(uint32_t*)(g_acth + (size_t)p1 * INTER + col) = v;
            }
        }
    }
}

// ---------------------------------------------------------------------------
// mlp2 (fp16): 128 pairs x 128 H cols, K=INTER, 3-stage. w * D -> g_o fp32.
__global__ void __launch_bounds__(256, 2) mlp2_tc() {
    int e = blockIdx.z;
    int cnt = g_cnt[e];
    int bm = blockIdx.x;
    if (bm * 128 >= cnt) return;
    int bn = blockIdx.y;
    __shared__ int sp[128];
    __shared__ float sw[128];
    int tid = threadIdx.x;
    if (tid < 128) {
        int r = bm * 128 + tid;
        int valid = (r < cnt);
        sp[tid] = valid ? g_list[e * TT + r] : -1;
        sw[tid] = valid ? g_w[e * TT + r] : 0.f;
    }
    __syncthreads();
    int wid = tid >> 5, lane = tid & 31;
    int wm = (wid >> 2) * 64, wn = (wid & 3) * 32;

    int lr0 = tid >> 3, q = tid & 7;
    const char* asrc[4];
    const char* bsrc[4];
#pragma unroll
    for (int i = 0; i < 4; ++i) {
        int r = lr0 + 32 * i;
        int p = sp[r];
        int pp = (p < 0) ? 0 : p;
        asrc[i] = (const char*)(g_acth + (size_t)pp * INTER) + q * 16;
        bsrc[i] = (const char*)(g_wdh + ((size_t)e * H + bn * 128 + r) * INTER) + q * 16;
    }
    uint32_t smb = smem_u32(smf);
    uint32_t dofs = (uint32_t)(lr0 * RB + q * 16);

    uint32_t aoff[4];
#pragma unroll
    for (int mt = 0; mt < 4; ++mt)
        aoff[mt] = (uint32_t)((wm + mt * 16 + (lane & 15)) * RB + ((lane >> 4) & 1) * 16);
    uint32_t boff[2];
#pragma unroll
    for (int p = 0; p < 2; ++p)
        boff[p] = (uint32_t)((wn + (2 * p + ((lane >> 3) >> 1)) * 8 + (lane & 7)) * RB +
                             ((lane >> 3) & 1) * 16);

    float acc[4][4][4] = {};

#define LOAD2(st, c) do { \
    uint32_t bb_ = smb + (st) * STG2 + dofs; \
    int kb_ = (c) * 128; \
    _Pragma("unroll") \
    for (int i_ = 0; i_ < 4; ++i_) { \
        uint32_t d_ = bb_ + i_ * (32 * RB); \
        cpasync16(d_, asrc[i_] + kb_); \
        cpasync16(d_ + TB2, bsrc[i_] + kb_); \
    } } while (0)

    LOAD2(0, 0); CP_COMMIT();
    LOAD2(1, 1); CP_COMMIT();
    const int NCH = INTER / BK2;  // 64
    for (int c = 0; c < NCH; ++c) {
        if (c < NCH - 1) { CP_WAIT(1); } else { CP_WAIT(0); }
        __syncthreads();
        if (c + 2 < NCH) { LOAD2((c + 2) % 3, c + 2); CP_COMMIT(); }
        uint32_t sA = smb + (c % 3) * STG2;
        uint32_t sB = sA + TB2;
#pragma unroll
        for (int ks = 0; ks < 4; ++ks) {
            uint32_t kb = ks * 32;
            uint32_t a[4][4], b[2][4];
#pragma unroll
            for (int mt = 0; mt < 4; ++mt) ldsm4(a[mt], sA + aoff[mt] + kb);
#pragma unroll
            for (int p = 0; p < 2; ++p) ldsm4(b[p], sB + boff[p] + kb);
#pragma unroll
            for (int nt = 0; nt < 4; ++nt) {
                const uint32_t* bp = &b[nt >> 1][(nt & 1) * 2];
#pragma unroll
                for (int mt = 0; mt < 4; ++mt) mma16f(acc[mt][nt], a[mt], bp);
            }
        }
    }
#undef LOAD2
    int g = lane >> 2, tc = lane & 3;
#pragma unroll
    for (int mt = 0; mt < 4; ++mt) {
        int r0 = wm + mt * 16 + g;
        int p0 = sp[r0], p1 = sp[r0 + 8];
        float w0 = sw[r0], w1 = sw[r0 + 8];
#pragma unroll
        for (int nt = 0; nt < 4; ++nt) {
            int col = bn * 128 + wn + nt * 8 + 2 * tc;
            if (p0 >= 0) {
                float2 v = { w0 * acc[mt][nt][0], w0 * acc[mt][nt][1] };
                *(float2*)(g_o + (size_t)p0 * H + col) = v;
            }
            if (p1 >= 0) {
                float2 v = { w1 * acc[mt][nt][2], w1 * acc[mt][nt][3] };
                *(float2*)(g_o + (size_t)p1 * H + col) = v;
            }
        }
    }
}

// out[t] += g_o[2t] + g_o[2t+1]
__global__ void __launch_bounds__(256) combine_kernel(float* __restrict__ C) {
    int v = blockIdx.x * blockDim.x + threadIdx.x;
    int t = v >> 8;
    int c = v & 255;
    const float4* go = (const float4*)g_o;
    float4 a = go[(size_t)(2 * t) * 256 + c];
    float4 b = go[(size_t)(2 * t) * 256 + 256 + c];
    float4* out = (float4*)C;
    float4 o = out[v];
    o.x += a.x + b.x; o.y += a.y + b.y; o.z += a.z + b.z; o.w += a.w + b.w;
    out[v] = o;
}

// ---------------------------------------------------------------------------
extern "C" void kernel_launch(void* const* d_in, const int* in_sizes, int n_in,
                              void* d_out, int out_size) {
    const float* x         = (const float*)d_in[0];
    const float* ln1_g     = (const float*)d_in[1];
    const float* ln1_b     = (const float*)d_in[2];
    const float* attn_w    = (const float*)d_in[3];
    const float* ln2_g     = (const float*)d_in[4];
    const float* ln2_b     = (const float*)d_in[5];
    const float* gate_w    = (const float*)d_in[6];
    const float* gate_proj = (const float*)d_in[7];
    const float* up_proj   = (const float*)d_in[8];
    const float* down_proj = (const float*)d_in[9];
    float* out = (float*)d_out;

    cudaFuncSetAttribute(attn3_tc, cudaFuncAttributeMaxDynamicSharedMemorySize, SMEMA);
    cudaFuncSetAttribute(mlp1_tc,  cudaFuncAttributeMaxDynamicSharedMemorySize, SMEM2);
    cudaFuncSetAttribute(mlp2_tc,  cudaFuncAttributeMaxDynamicSharedMemorySize, SMEM2);

    const int n4w = NE * INTER * H / 4;  // 8388608

    zero_cnt_kernel<<<1, 32>>>();
    wconv_k<<<dim3(n4w / 256, 3), 256>>>((const float4*)gate_proj,
                                         (const float4*)up_proj,
                                         (const float4*)down_proj, n4w);

    ln_kernel<<<TT, 256>>>(x, ln1_g, ln1_b, 0);                             // g_tn = LN1(x)
    attn3_tc<<<dim3(TT / 128, H / 128), 256, SMEMA>>>(attn_w, x, out);      // out = h
    ln_kernel<<<TT, 256>>>(out, ln2_g, ln2_b, 1);                           // g_tn fp32 + g_tnh fp16
    gate_topk_kernel<<<TT / 8, 256>>>(gate_w);                              // fp32 gating
    mlp1_tc<<<dim3(TT / 128, INTER / 64, NE), 256, SMEM2>>>();
    mlp2_tc<<<dim3(TT / 128, H / 128, NE), 256, SMEM2>>>();
    combine_kernel<<<(TT * H / 4) / 256, 256>>>(out);
}

// round 7
// speedup vs baseline: 9.5142x; 1.0558x over previous
#include <cuda_runtime.h>
#include <cuda_fp16.h>
#include <math.h>
#include <stdint.h>

#define H     1024
#define INTER 4096
#define NE    8
#define TT    8192
#define LNEPS 1e-5f

// fp16 tiling: 128-row tiles, 64-half K chunks, 144B padded rows
#define BK2    64
#define RB     144                   // bytes per smem row (64*2 + 16 pad)
#define TB2    (128 * RB)            // 18432 bytes per tile
#define STG2   (2 * TB2)             // mlp: A + B per stage = 36864
#define SMEM2  (3 * STG2)            // 110592 (3-stage)
#define STGA   (4 * TB2)             // attn: Ah, Al, Bh, Bl per stage = 73728
#define SMEMA  (3 * STGA)            // 221184 (3-stage)

// ---------------- scratch (static device globals) ---------------------------
__device__ __half g_tnhh[(size_t)TT * H];                // LN1 out hi fp16
__device__ __half g_tnhl[(size_t)TT * H];                // LN1 out lo fp16
__device__ __half g_tnh[(size_t)TT * H];                 // LN2 out fp16
__device__ __half g_acth[(size_t)TT * 2 * INTER];        // silu(g)*u fp16 per pair
__device__ float  g_o[(size_t)TT * 2 * H];               // per-pair weighted down out
__device__ int    g_cnt[NE];
__device__ int    g_list[NE * TT];
__device__ float  g_w[NE * TT];
__device__ __half g_wh[(size_t)H * H];                   // attn_w hi fp16
__device__ __half g_wl[(size_t)H * H];                   // attn_w lo fp16
__device__ __half g_wgh[(size_t)NE * INTER * H];         // fp16 weight copies
__device__ __half g_wuh[(size_t)NE * INTER * H];
__device__ __half g_wdh[(size_t)NE * H * INTER];

// ---------------- helpers ---------------------------------------------------
__device__ __forceinline__ uint32_t smem_u32(const void* p) {
    uint32_t a;
    asm("{ .reg .u64 t; cvta.to.shared.u64 t, %1; cvt.u32.u64 %0, t; }" : "=r"(a) : "l"(p));
    return a;
}
__device__ __forceinline__ uint32_t pkhf(float lo, float hi) {
    uint32_t r;
    asm("cvt.rn.f16x2.f32 %0, %1, %2;" : "=r"(r) : "f"(hi), "f"(lo));
    return r;
}
__device__ __forceinline__ void cpasync16(uint32_t s, const void* g) {
    asm volatile("cp.async.cg.shared.global [%0], [%1], 16;" :: "r"(s), "l"(g));
}
#define CP_COMMIT() asm volatile("cp.async.commit_group;" ::: "memory")
#define CP_WAIT(n)  asm volatile("cp.async.wait_group %0;" :: "n"(n) : "memory")

__device__ __forceinline__ void ldsm4(uint32_t* r, uint32_t addr) {
    asm volatile("ldmatrix.sync.aligned.m8n8.x4.shared.b16 {%0,%1,%2,%3}, [%4];"
                 : "=r"(r[0]), "=r"(r[1]), "=r"(r[2]), "=r"(r[3]) : "r"(addr));
}
__device__ __forceinline__ void mma16f(float* c, const uint32_t* a, const uint32_t* b) {
    asm volatile(
        "mma.sync.aligned.m16n8k16.row.col.f32.f16.f16.f32 "
        "{%0,%1,%2,%3}, {%4,%5,%6,%7}, {%8,%9}, {%0,%1,%2,%3};"
        : "+f"(c[0]), "+f"(c[1]), "+f"(c[2]), "+f"(c[3])
        : "r"(a[0]), "r"(a[1]), "r"(a[2]), "r"(a[3]), "r"(b[0]), "r"(b[1]));
}

// ---------------------------------------------------------------------------
__global__ void zero_cnt_kernel() {
    if (threadIdx.x < NE) g_cnt[threadIdx.x] = 0;
}

// fp32 -> fp16 MoE weight copies; blockIdx.y selects target (0=gate,1=up,2=down)
__global__ void __launch_bounds__(256) wconv_k(const float4* __restrict__ sg,
                                               const float4* __restrict__ su,
                                               const float4* __restrict__ sd, int n4) {
    int i = blockIdx.x * blockDim.x + threadIdx.x;
    if (i >= n4) return;
    int which = blockIdx.y;
    const float4* s = (which == 0) ? sg : (which == 1) ? su : sd;
    float4 v = s[i];
    uint2 o = { pkhf(v.x, v.y), pkhf(v.z, v.w) };
    __half* dst = (which == 0) ? g_wgh : (which == 1) ? g_wuh : g_wdh;
    ((uint2*)dst)[i] = o;
}

// attn_w fp32 -> hi/lo fp16 split
__global__ void __launch_bounds__(256) wsplit_k(const float4* __restrict__ s, int n4) {
    int i = blockIdx.x * blockDim.x + threadIdx.x;
    if (i >= n4) return;
    float4 v = s[i];
    float hx = __half2float(__float2half_rn(v.x));
    float hy = __half2float(__float2half_rn(v.y));
    float hz = __half2float(__float2half_rn(v.z));
    float hw = __half2float(__float2half_rn(v.w));
    ((uint2*)g_wh)[i] = { pkhf(hx, hy), pkhf(hz, hw) };
    ((uint2*)g_wl)[i] = { pkhf(v.x - hx, v.y - hy), pkhf(v.z - hz, v.w - hw) };
}

// LN1: writes hi/lo fp16 decomposition (for split-fp16 attn GEMM)
__global__ void __launch_bounds__(256) ln1_kernel(const float* __restrict__ src,
                                                  const float* __restrict__ gamma,
                                                  const float* __restrict__ beta) {
    int row = blockIdx.x;
    int tid = threadIdx.x;
    const float4 xv = ((const float4*)(src + (size_t)row * H))[tid];
    float s = xv.x + xv.y + xv.z + xv.w;
    float q = xv.x * xv.x + xv.y * xv.y + xv.z * xv.z + xv.w * xv.w;
#pragma unroll
    for (int o = 16; o; o >>= 1) {
        s += __shfl_xor_sync(0xffffffffu, s, o);
        q += __shfl_xor_sync(0xffffffffu, q, o);
    }
    __shared__ float ss[8], sq[8];
    __shared__ float sm_, sr_;
    int w = tid >> 5;
    if ((tid & 31) == 0) { ss[w] = s; sq[w] = q; }
    __syncthreads();
    if (tid == 0) {
        float S = 0.f, Q = 0.f;
#pragma unroll
        for (int i = 0; i < 8; ++i) { S += ss[i]; Q += sq[i]; }
        float m = S * (1.0f / H);
        float v = Q * (1.0f / H) - m * m;
        sm_ = m;
        sr_ = rsqrtf(v + LNEPS);
    }
    __syncthreads();
    float m = sm_, r = sr_;
    const float4 gv = ((const float4*)gamma)[tid];
    const float4 bv = ((const float4*)beta)[tid];
    float4 o;
    o.x = (xv.x - m) * r * gv.x + bv.x;
    o.y = (xv.y - m) * r * gv.y + bv.y;
    o.z = (xv.z - m) * r * gv.z + bv.z;
    o.w = (xv.w - m) * r * gv.w + bv.w;
    float hx = __half2float(__float2half_rn(o.x));
    float hy = __half2float(__float2half_rn(o.y));
    float hz = __half2float(__float2half_rn(o.z));
    float hw = __half2float(__float2half_rn(o.w));
    ((uint2*)(g_tnhh + (size_t)row * H))[tid] = { pkhf(hx, hy), pkhf(hz, hw) };
    ((uint2*)(g_tnhl + (size_t)row * H))[tid] =
        { pkhf(o.x - hx, o.y - hy), pkhf(o.z - hz, o.w - hw) };
}

// LN2 fused with gate + top-2 + softmax + scatter. Writes fp16 LN2 out only.
__global__ void __launch_bounds__(256) ln2_gate_kernel(const float* __restrict__ src,
                                                       const float* __restrict__ gamma,
                                                       const float* __restrict__ beta,
                                                       const float* __restrict__ gw) {
    int row = blockIdx.x;
    int tid = threadIdx.x;
    const float4 xv = ((const float4*)(src + (size_t)row * H))[tid];
    float s = xv.x + xv.y + xv.z + xv.w;
    float q = xv.x * xv.x + xv.y * xv.y + xv.z * xv.z + xv.w * xv.w;
#pragma unroll
    for (int o = 16; o; o >>= 1) {
        s += __shfl_xor_sync(0xffffffffu, s, o);
        q += __shfl_xor_sync(0xffffffffu, q, o);
    }
    __shared__ float ss[8], sq[8];
    __shared__ float sm_, sr_;
    __shared__ float red[8][NE];
    int w = tid >> 5, lane = tid & 31;
    if (lane == 0) { ss[w] = s; sq[w] = q; }
    __syncthreads();
    if (tid == 0) {
        float S = 0.f, Q = 0.f;
#pragma unroll
        for (int i = 0; i < 8; ++i) { S += ss[i]; Q += sq[i]; }
        float m = S * (1.0f / H);
        float v = Q * (1.0f / H) - m * m;
        sm_ = m;
        sr_ = rsqrtf(v + LNEPS);
    }
    __syncthreads();
    float m = sm_, r = sr_;
    const float4 gv = ((const float4*)gamma)[tid];
    const float4 bv = ((const float4*)beta)[tid];
    float4 o;
    o.x = (xv.x - m) * r * gv.x + bv.x;
    o.y = (xv.y - m) * r * gv.y + bv.y;
    o.z = (xv.z - m) * r * gv.z + bv.z;
    o.w = (xv.w - m) * r * gv.w + bv.w;
    ((uint2*)(g_tnh + (size_t)row * H))[tid] = { pkhf(o.x, o.y), pkhf(o.z, o.w) };
    // gate logits: each thread contributes its 4 columns for all 8 experts
    float part[NE];
#pragma unroll
    for (int e = 0; e < NE; ++e) {
        float4 g4 = ((const float4*)(gw + e * H))[tid];
        part[e] = o.x * g4.x + o.y * g4.y + o.z * g4.z + o.w * g4.w;
    }
#pragma unroll
    for (int off = 16; off; off >>= 1)
#pragma unroll
        for (int e = 0; e < NE; ++e) part[e] += __shfl_xor_sync(0xffffffffu, part[e], off);
    if (lane == 0)
#pragma unroll
        for (int e = 0; e < NE; ++e) red[w][e] = part[e];
    __syncthreads();
    if (tid == 0) {
        float lg[NE];
#pragma unroll
        for (int e = 0; e < NE; ++e) {
            float acc = 0.f;
#pragma unroll
            for (int i = 0; i < 8; ++i) acc += red[i][e];
            lg[e] = acc;
        }
        float v0 = -INFINITY; int i0 = 0;
#pragma unroll
        for (int e = 0; e < NE; ++e) if (lg[e] > v0) { v0 = lg[e]; i0 = e; }
        float v1 = -INFINITY; int i1 = 0;
#pragma unroll
        for (int e = 0; e < NE; ++e) if (e != i0 && lg[e] > v1) { v1 = lg[e]; i1 = e; }
        float ex = expf(v1 - v0);
        float w0 = 1.0f / (1.0f + ex);
        float w1 = ex / (1.0f + ex);
        int p0 = atomicAdd(&g_cnt[i0], 1);
        g_list[i0 * TT + p0] = row * 2 + 0;
        g_w[i0 * TT + p0] = w0;
        int p1 = atomicAdd(&g_cnt[i1], 1);
        g_list[i1 * TT + p1] = row * 2 + 1;
        g_w[i1 * TT + p1] = w1;
    }
}

extern __shared__ float smf[];

// ---------------------------------------------------------------------------
// attn (fp16 split, pipelined): C = X + tn @ W^T, D = Ah·Bh + Ah·Bl + Al·Bh.
// 3-stage cp.async, 4 tiles/stage (Ah, Al, Bh, Bl).
__global__ void __launch_bounds__(256) attn_f16(const float* __restrict__ X,
                                                float* __restrict__ C) {
    int tid = threadIdx.x;
    int bm = blockIdx.x, bn = blockIdx.y;
    int wid = tid >> 5, lane = tid & 31;
    int wm = (wid >> 2) * 64, wn = (wid & 3) * 32;

    int lr0 = tid >> 3, q = tid & 7;
    const char* src[4][4];   // [tile][i]
#pragma unroll
    for (int i = 0; i < 4; ++i) {
        int r = lr0 + 32 * i;
        src[0][i] = (const char*)(g_tnhh + (size_t)(bm * 128 + r) * H) + q * 16;
        src[1][i] = (const char*)(g_tnhl + (size_t)(bm * 128 + r) * H) + q * 16;
        src[2][i] = (const char*)(g_wh + (size_t)(bn * 128 + r) * H) + q * 16;
        src[3][i] = (const char*)(g_wl + (size_t)(bn * 128 + r) * H) + q * 16;
    }
    uint32_t smb = smem_u32(smf);
    uint32_t dofs = (uint32_t)(lr0 * RB + q * 16);

    uint32_t aoff[4];
#pragma unroll
    for (int mt = 0; mt < 4; ++mt)
        aoff[mt] = (uint32_t)((wm + mt * 16 + (lane & 15)) * RB + ((lane >> 4) & 1) * 16);
    uint32_t boff[2];
#pragma unroll
    for (int p = 0; p < 2; ++p)
        boff[p] = (uint32_t)((wn + (2 * p + ((lane >> 3) >> 1)) * 8 + (lane & 7)) * RB +
                             ((lane >> 3) & 1) * 16);

    float acc[4][4][4] = {};

#define LOADA(st, c) do { \
    uint32_t bb_ = smb + (st) * STGA + dofs; \
    int kb_ = (c) * 128; \
    _Pragma("unroll") \
    for (int t_ = 0; t_ < 4; ++t_) { \
        _Pragma("unroll") \
        for (int i_ = 0; i_ < 4; ++i_) \
            cpasync16(bb_ + t_ * TB2 + i_ * (32 * RB), src[t_][i_] + kb_); \
    } } while (0)

    LOADA(0, 0); CP_COMMIT();
    LOADA(1, 1); CP_COMMIT();
    const int NCH = H / BK2;  // 16
    for (int c = 0; c < NCH; ++c) {
        if (c < NCH - 1) { CP_WAIT(1); } else { CP_WAIT(0); }
        __syncthreads();
        if (c + 2 < NCH) { LOADA((c + 2) % 3, c + 2); CP_COMMIT(); }
        uint32_t sA = smb + (c % 3) * STGA;
#pragma unroll
        for (int ks = 0; ks < 4; ++ks) {
            uint32_t kb = ks * 32;
            uint32_t ah[4][4], al[4][4], bh[2][4], bl[2][4];
#pragma unroll
            for (int mt = 0; mt < 4; ++mt) {
                ldsm4(ah[mt], sA + aoff[mt] + kb);
                ldsm4(al[mt], sA + TB2 + aoff[mt] + kb);
            }
#pragma unroll
            for (int p = 0; p < 2; ++p) {
                ldsm4(bh[p], sA + 2 * TB2 + boff[p] + kb);
                ldsm4(bl[p], sA + 3 * TB2 + boff[p] + kb);
            }
#pragma unroll
            for (int nt = 0; nt < 4; ++nt) {
                const uint32_t* bhp = &bh[nt >> 1][(nt & 1) * 2];
                const uint32_t* blp = &bl[nt >> 1][(nt & 1) * 2];
#pragma unroll
                for (int mt = 0; mt < 4; ++mt) {
                    mma16f(acc[mt][nt], ah[mt], bhp);
                    mma16f(acc[mt][nt], ah[mt], blp);
                    mma16f(acc[mt][nt], al[mt], bhp);
                }
            }
        }
    }
#undef LOADA
    int g = lane >> 2, tc = lane & 3;
#pragma unroll
    for (int mt = 0; mt < 4; ++mt) {
        int row0 = bm * 128 + wm + mt * 16 + g;
#pragma unroll
        for (int nt = 0; nt < 4; ++nt) {
            int col = bn * 128 + wn + nt * 8 + 2 * tc;
            float2 x0 = *(const float2*)(X + (size_t)row0 * H + col);
            float2 o0 = { x0.x + acc[mt][nt][0], x0.y + acc[mt][nt][1] };
            *(float2*)(C + (size_t)row0 * H + col) = o0;
            float2 x1 = *(const float2*)(X + (size_t)(row0 + 8) * H + col);
            float2 o1 = { x1.x + acc[mt][nt][2], x1.y + acc[mt][nt][3] };
            *(float2*)(C + (size_t)(row0 + 8) * H + col) = o1;
        }
    }
}

// ---------------------------------------------------------------------------
// mlp1 (fp16): 128 pairs x 64 inter, B = [64 gate ; 64 up], 3-stage cp.async.
__global__ void __launch_bounds__(256, 2) mlp1_tc() {
    int e = blockIdx.z;
    int cnt = g_cnt[e];
    int bm = blockIdx.x;
    if (bm * 128 >= cnt) return;
    int ib = blockIdx.y;
    __shared__ int sp[128];
    int tid = threadIdx.x;
    if (tid < 128) {
        int r = bm * 128 + tid;
        sp[tid] = (r < cnt) ? g_list[e * TT + r] : -1;
    }
    __syncthreads();
    int wid = tid >> 5, lane = tid & 31;
    int wm = (wid >> 2) * 64, wn = (wid & 3) * 16;

    int lr0 = tid >> 3, q = tid & 7;
    const char* asrc[4];
    const char* bsrc[4];
#pragma unroll
    for (int i = 0; i < 4; ++i) {
        int r = lr0 + 32 * i;
        int p = sp[r];
        int t = (p < 0) ? 0 : (p >> 1);
        asrc[i] = (const char*)(g_tnh + (size_t)t * H) + q * 16;
        const __half* wsrc = (r < 64)
            ? (g_wgh + ((size_t)e * INTER + ib * 64 + r) * H)
            : (g_wuh + ((size_t)e * INTER + ib * 64 + (r - 64)) * H);
        bsrc[i] = (const char*)wsrc + q * 16;
    }
    uint32_t smb = smem_u32(smf);
    uint32_t dofs = (uint32_t)(lr0 * RB + q * 16);

    uint32_t aoff[4];
#pragma unroll
    for (int mt = 0; mt < 4; ++mt)
        aoff[mt] = (uint32_t)((wm + mt * 16 + (lane & 15)) * RB + ((lane >> 4) & 1) * 16);
    uint32_t boff = (uint32_t)((wn + ((lane >> 3) >> 1) * 8 + (lane & 7)) * RB +
                               ((lane >> 3) & 1) * 16);

    float accg[4][2][4] = {}, accu[4][2][4] = {};

#define LOAD1(st, c) do { \
    uint32_t bb_ = smb + (st) * STG2 + dofs; \
    int kb_ = (c) * 128; \
    _Pragma("unroll") \
    for (int i_ = 0; i_ < 4; ++i_) { \
        uint32_t d_ = bb_ + i_ * (32 * RB); \
        cpasync16(d_, asrc[i_] + kb_); \
        cpasync16(d_ + TB2, bsrc[i_] + kb_); \
    } } while (0)

    LOAD1(0, 0); CP_COMMIT();
    LOAD1(1, 1); CP_COMMIT();
    const int NCH = H / BK2;  // 16
    for (int c = 0; c < NCH; ++c) {
        if (c < NCH - 1) { CP_WAIT(1); } else { CP_WAIT(0); }
        __syncthreads();
        if (c + 2 < NCH) { LOAD1((c + 2) % 3, c + 2); CP_COMMIT(); }
        uint32_t sA = smb + (c % 3) * STG2;
        uint32_t sB = sA + TB2;
#pragma unroll
        for (int ks = 0; ks < 4; ++ks) {
            uint32_t kb = ks * 32;
            uint32_t a[4][4], bg[4], bu[4];
#pragma unroll
            for (int mt = 0; mt < 4; ++mt) ldsm4(a[mt], sA + aoff[mt] + kb);
            ldsm4(bg, sB + boff + kb);
            ldsm4(bu, sB + 64 * RB + boff + kb);
#pragma unroll
            for (int nt = 0; nt < 2; ++nt) {
#pragma unroll
                for (int mt = 0; mt < 4; ++mt) {
                    mma16f(accg[mt][nt], a[mt], &bg[nt * 2]);
                    mma16f(accu[mt][nt], a[mt], &bu[nt * 2]);
                }
            }
        }
    }
#undef LOAD1
    int g = lane >> 2, tc = lane & 3;
#pragma unroll
    for (int mt = 0; mt < 4; ++mt) {
        int r0 = wm + mt * 16 + g;
        int p0 = sp[r0], p1 = sp[r0 + 8];
#pragma unroll
        for (int nt = 0; nt < 2; ++nt) {
            int col = ib * 64 + wn + nt * 8 + 2 * tc;
            if (p0 >= 0) {
                float g0 = accg[mt][nt][0], u0 = accu[mt][nt][0];
                float g1 = accg[mt][nt][1], u1 = accu[mt][nt][1];
                uint32_t v = pkhf(g0 / (1.f + expf(-g0)) * u0,
                                  g1 / (1.f + expf(-g1)) * u1);
                *(uint32_t*)(g_acth + (size_t)p0 * INTER + col) = v;
            }
            if (p1 >= 0) {
                float g2 = accg[mt][nt][2], u2 = accu[mt][nt][2];
                float g3 = accg[mt][nt][3], u3 = accu[mt][nt][3];
                uint32_t v = pkhf(g2 / (1.f + expf(-g2)) * u2,
                                  g3 / (1.f + expf(-g3)) * u3);
                *(uint32_t*)(g_acth + (size_t)p1 * INTER + col) = v;
            }
        }
    }
}

// ---------------------------------------------------------------------------
// mlp2 (fp16): 128 pairs x 128 H cols, K=INTER, 3-stage. w * D -> g_o fp32.
__global__ void __launch_bounds__(256, 2) mlp2_tc() {
    int e = blockIdx.z;
    int cnt = g_cnt[e];
    int bm = blockIdx.x;
    if (bm * 128 >= cnt) return;
    int bn = blockIdx.y;
    __shared__ int sp[128];
    __shared__ float sw[128];
    int tid = threadIdx.x;
    if (tid < 128) {
        int r = bm * 128 + tid;
        int valid = (r < cnt);
        sp[tid] = valid ? g_list[e * TT + r] : -1;
        sw[tid] = valid ? g_w[e * TT + r] : 0.f;
    }
    __syncthreads();
    int wid = tid >> 5, lane = tid & 31;
    int wm = (wid >> 2) * 64, wn = (wid & 3) * 32;

    int lr0 = tid >> 3, q = tid & 7;
    const char* asrc[4];
    const char* bsrc[4];
#pragma unroll
    for (int i = 0; i < 4; ++i) {
        int r = lr0 + 32 * i;
        int p = sp[r];
        int pp = (p < 0) ? 0 : p;
        asrc[i] = (const char*)(g_acth + (size_t)pp * INTER) + q * 16;
        bsrc[i] = (const char*)(g_wdh + ((size_t)e * H + bn * 128 + r) * INTER) + q * 16;
    }
    uint32_t smb = smem_u32(smf);
    uint32_t dofs = (uint32_t)(lr0 * RB + q * 16);

    uint32_t aoff[4];
#pragma unroll
    for (int mt = 0; mt < 4; ++mt)
        aoff[mt] = (uint32_t)((wm + mt * 16 + (lane & 15)) * RB + ((lane >> 4) & 1) * 16);
    uint32_t boff[2];
#pragma unroll
    for (int p = 0; p < 2; ++p)
        boff[p] = (uint32_t)((wn + (2 * p + ((lane >> 3) >> 1)) * 8 + (lane & 7)) * RB +
                             ((lane >> 3) & 1) * 16);

    float acc[4][4][4] = {};

#define LOAD2(st, c) do { \
    uint32_t bb_ = smb + (st) * STG2 + dofs; \
    int kb_ = (c) * 128; \
    _Pragma("unroll") \
    for (int i_ = 0; i_ < 4; ++i_) { \
        uint32_t d_ = bb_ + i_ * (32 * RB); \
        cpasync16(d_, asrc[i_] + kb_); \
        cpasync16(d_ + TB2, bsrc[i_] + kb_); \
    } } while (0)

    LOAD2(0, 0); CP_COMMIT();
    LOAD2(1, 1); CP_COMMIT();
    const int NCH = INTER / BK2;  // 64
    for (int c = 0; c < NCH; ++c) {
        if (c < NCH - 1) { CP_WAIT(1); } else { CP_WAIT(0); }
        __syncthreads();
        if (c + 2 < NCH) { LOAD2((c + 2) % 3, c + 2); CP_COMMIT(); }
        uint32_t sA = smb + (c % 3) * STG2;
        uint32_t sB = sA + TB2;
#pragma unroll
        for (int ks = 0; ks < 4; ++ks) {
            uint32_t kb = ks * 32;
            uint32_t a[4][4], b[2][4];
#pragma unroll
            for (int mt = 0; mt < 4; ++mt) ldsm4(a[mt], sA + aoff[mt] + kb);
#pragma unroll
            for (int p = 0; p < 2; ++p) ldsm4(b[p], sB + boff[p] + kb);
#pragma unroll
            for (int nt = 0; nt < 4; ++nt) {
                const uint32_t* bp = &b[nt >> 1][(nt & 1) * 2];
#pragma unroll
                for (int mt = 0; mt < 4; ++mt) mma16f(acc[mt][nt], a[mt], bp);
            }
        }
    }
#undef LOAD2
    int g = lane >> 2, tc = lane & 3;
#pragma unroll
    for (int mt = 0; mt < 4; ++mt) {
        int r0 = wm + mt * 16 + g;
        int p0 = sp[r0], p1 = sp[r0 + 8];
        float w0 = sw[r0], w1 = sw[r0 + 8];
#pragma unroll
        for (int nt = 0; nt < 4; ++nt) {
            int col = bn * 128 + wn + nt * 8 + 2 * tc;
            if (p0 >= 0) {
                float2 v = { w0 * acc[mt][nt][0], w0 * acc[mt][nt][1] };
                *(float2*)(g_o + (size_t)p0 * H + col) = v;
            }
            if (p1 >= 0) {
                float2 v = { w1 * acc[mt][nt][2], w1 * acc[mt][nt][3] };
                *(float2*)(g_o + (size_t)p1 * H + col) = v;
            }
        }
    }
}

// out[t] += g_o[2t] + g_o[2t+1]
__global__ void __launch_bounds__(256) combine_kernel(float* __restrict__ C) {
    int v = blockIdx.x * blockDim.x + threadIdx.x;
    int t = v >> 8;
    int c = v & 255;
    const float4* go = (const float4*)g_o;
    float4 a = go[(size_t)(2 * t) * 256 + c];
    float4 b = go[(size_t)(2 * t) * 256 + 256 + c];
    float4* out = (float4*)C;
    float4 o = out[v];
    o.x += a.x + b.x; o.y += a.y + b.y; o.z += a.z + b.z; o.w += a.w + b.w;
    out[v] = o;
}

// ---------------------------------------------------------------------------
extern "C" void kernel_launch(void* const* d_in, const int* in_sizes, int n_in,
                              void* d_out, int out_size) {
    const float* x         = (const float*)d_in[0];
    const float* ln1_g     = (const float*)d_in[1];
    const float* ln1_b     = (const float*)d_in[2];
    const float* attn_w    = (const float*)d_in[3];
    const float* ln2_g     = (const float*)d_in[4];
    const float* ln2_b     = (const float*)d_in[5];
    const float* gate_w    = (const float*)d_in[6];
    const float* gate_proj = (const float*)d_in[7];
    const float* up_proj   = (const float*)d_in[8];
    const float* down_proj = (const float*)d_in[9];
    float* out = (float*)d_out;

    cudaFuncSetAttribute(attn_f16, cudaFuncAttributeMaxDynamicSharedMemorySize, SMEMA);
    cudaFuncSetAttribute(mlp1_tc,  cudaFuncAttributeMaxDynamicSharedMemorySize, SMEM2);
    cudaFuncSetAttribute(mlp2_tc,  cudaFuncAttributeMaxDynamicSharedMemorySize, SMEM2);

    const int n4w = NE * INTER * H / 4;  // 8388608
    const int n4a = H * H / 4;           // 262144

    zero_cnt_kernel<<<1, 32>>>();
    wconv_k<<<dim3(n4w / 256, 3), 256>>>((const float4*)gate_proj,
                                         (const float4*)up_proj,
                                         (const float4*)down_proj, n4w);
    wsplit_k<<<n4a / 256, 256>>>((const float4*)attn_w, n4a);

    ln1_kernel<<<TT, 256>>>(x, ln1_g, ln1_b);                       // tn hi/lo fp16
    attn_f16<<<dim3(TT / 128, H / 128), 256, SMEMA>>>(x, out);      // out = h
    ln2_gate_kernel<<<TT, 256>>>(out, ln2_g, ln2_b, gate_w);        // g_tnh + routing
    mlp1_tc<<<dim3(TT / 128, INTER / 64, NE), 256, SMEM2>>>();
    mlp2_tc<<<dim3(TT / 128, H / 128, NE), 256, SMEM2>>>();
    combine_kernel<<<(TT * H / 4) / 256, 256>>>(out);
}